// round 2
// baseline (speedup 1.0000x reference)
#include <cuda_runtime.h>

#define N_NODES 50000
#define N_EDGES 800000
#define HIDDEN 64
#define OUT_DIM 16

// Scratch (device globals; no allocation allowed)
__device__ float g_deg[N_NODES];
__device__ float g_agg[N_NODES * HIDDEN];
__device__ float g_h0[N_NODES * HIDDEN];
__device__ float g_h1[N_NODES * HIDDEN];

// Zero degree + aggregation buffers
__global__ void zero_all_kernel() {
    int i = blockIdx.x * blockDim.x + threadIdx.x;
    int total = N_NODES * HIDDEN;
    for (; i < total; i += gridDim.x * blockDim.x) {
        g_agg[i] = 0.0f;
        if (i < N_NODES) g_deg[i] = 0.0f;
    }
}

// Zero only the aggregation buffer (between layers)
__global__ void zero_agg_kernel() {
    int i = blockIdx.x * blockDim.x + threadIdx.x;
    int total = N_NODES * HIDDEN;
    for (; i < total; i += gridDim.x * blockDim.x) {
        g_agg[i] = 0.0f;
    }
}

// In-degree via atomics (edge_index is int32: JAX x64-disabled downcasts int64)
__global__ void deg_kernel(const int* __restrict__ ei) {
    int e = blockIdx.x * blockDim.x + threadIdx.x;
    if (e >= N_EDGES) return;
    int dst = ei[N_EDGES + e];
    atomicAdd(&g_deg[dst], 1.0f);
}

// Gather x[src] and atomically scatter-add into agg[dst]
// thread = (edge, feature); 64 threads per edge -> coalesced gather & scatter
__global__ void scatter_kernel(const float* __restrict__ xin,
                               const int* __restrict__ ei) {
    long long tid = (long long)blockIdx.x * blockDim.x + threadIdx.x;
    if (tid >= (long long)N_EDGES * HIDDEN) return;
    int e = (int)(tid >> 6);
    int f = (int)(tid & 63);
    int src = __ldg(&ei[e]);
    int dst = __ldg(&ei[N_EDGES + e]);
    float v = __ldg(&xin[(long long)src * HIDDEN + f]);
    atomicAdd(&g_agg[(long long)dst * HIDDEN + f], v);
}

// y = relu( (agg/deg) @ Wl + bl + x @ Wr )
// thread = (node, out_feature)
__global__ void node_update_kernel(const float* __restrict__ xin,
                                   const float* __restrict__ Wl,
                                   const float* __restrict__ bl,
                                   const float* __restrict__ Wr,
                                   float* __restrict__ xout) {
    int tid = blockIdx.x * blockDim.x + threadIdx.x;
    if (tid >= N_NODES * HIDDEN) return;
    int n = tid >> 6;
    int f = tid & 63;

    float d = g_deg[n];
    d = d < 1.0f ? 1.0f : d;
    float invd = 1.0f / d;

    const float* aggn = &g_agg[(long long)n * HIDDEN];
    const float* xn = &xin[(long long)n * HIDDEN];

    float acc_l = 0.0f;
    float acc_r = 0.0f;
#pragma unroll
    for (int k = 0; k < HIDDEN; k++) {
        acc_l = fmaf(__ldg(&aggn[k]), __ldg(&Wl[k * HIDDEN + f]), acc_l);
        acc_r = fmaf(__ldg(&xn[k]), __ldg(&Wr[k * HIDDEN + f]), acc_r);
    }
    float y = fmaf(acc_l, invd, acc_r) + __ldg(&bl[f]);
    xout[tid] = y > 0.0f ? y : 0.0f;
}

// out = x @ W_out + b_out ; thread = (node, out_col)
__global__ void out_kernel(const float* __restrict__ xin,
                           const float* __restrict__ Wout,
                           const float* __restrict__ bout,
                           float* __restrict__ out) {
    int tid = blockIdx.x * blockDim.x + threadIdx.x;
    if (tid >= N_NODES * OUT_DIM) return;
    int n = tid >> 4;
    int o = tid & 15;
    const float* xn = &xin[(long long)n * HIDDEN];
    float acc = __ldg(&bout[o]);
#pragma unroll
    for (int k = 0; k < HIDDEN; k++) {
        acc = fmaf(__ldg(&xn[k]), __ldg(&Wout[k * OUT_DIM + o]), acc);
    }
    out[tid] = acc;
}

extern "C" void kernel_launch(void* const* d_in, const int* in_sizes, int n_in,
                              void* d_out, int out_size) {
    const float* x = (const float*)d_in[0];
    const int* ei = (const int*)d_in[1];
    const float* Wl = (const float*)d_in[2];
    const float* bl = (const float*)d_in[3];
    const float* Wr = (const float*)d_in[4];
    const float* Wout = (const float*)d_in[5];
    const float* bout = (const float*)d_in[6];
    float* out = (float*)d_out;

    const int TPB = 256;
    const int zero_blocks = 2048;
    const long long scatter_threads = (long long)N_EDGES * HIDDEN;
    const int scatter_blocks = (int)((scatter_threads + TPB - 1) / TPB);
    const int node_blocks = (N_NODES * HIDDEN + TPB - 1) / TPB;
    const int deg_blocks = (N_EDGES + TPB - 1) / TPB;
    const int out_blocks = (N_NODES * OUT_DIM + TPB - 1) / TPB;

    // init
    zero_all_kernel<<<zero_blocks, TPB>>>();
    deg_kernel<<<deg_blocks, TPB>>>(ei);

    // layer 0: x -> g_h0
    scatter_kernel<<<scatter_blocks, TPB>>>(x, ei);
    node_update_kernel<<<node_blocks, TPB>>>(x, Wl, bl, Wr, g_h0);

    // layer 1: g_h0 -> g_h1
    zero_agg_kernel<<<zero_blocks, TPB>>>();
    scatter_kernel<<<scatter_blocks, TPB>>>(g_h0, ei);
    node_update_kernel<<<node_blocks, TPB>>>(
        g_h0, Wl + HIDDEN * HIDDEN, bl + HIDDEN, Wr + HIDDEN * HIDDEN, g_h1);

    // layer 2: g_h1 -> g_h0
    zero_agg_kernel<<<zero_blocks, TPB>>>();
    scatter_kernel<<<scatter_blocks, TPB>>>(g_h1, ei);
    node_update_kernel<<<node_blocks, TPB>>>(
        g_h1, Wl + 2 * HIDDEN * HIDDEN, bl + 2 * HIDDEN, Wr + 2 * HIDDEN * HIDDEN, g_h0);

    // output projection
    out_kernel<<<out_blocks, TPB>>>(g_h0, Wout, bout, out);
}

// round 3
// speedup vs baseline: 1.0422x; 1.0422x over previous
#include <cuda_runtime.h>

#define N_NODES 50000
#define N_EDGES 800000
#define HIDDEN 64
#define OUT_DIM 16

// ---------------- device scratch (no allocs allowed) ----------------
__device__ int g_count[N_NODES];        // histogram, then reused as fill cursor
__device__ int g_off[N_NODES + 1];      // CSR row offsets
__device__ int g_csr_src[N_EDGES];      // CSR column (src) indices
__device__ __align__(16) float g_agg[N_NODES * HIDDEN];
__device__ __align__(16) float g_h0[N_NODES * HIDDEN];
__device__ __align__(16) float g_h1[N_NODES * HIDDEN];

// ---------------- CSR construction ----------------
__global__ void zero_count_kernel() {
    int i = blockIdx.x * blockDim.x + threadIdx.x;
    if (i < N_NODES) g_count[i] = 0;
}

__global__ void hist_kernel(const int* __restrict__ ei) {
    int e = blockIdx.x * blockDim.x + threadIdx.x;
    if (e >= N_EDGES) return;
    atomicAdd(&g_count[ei[N_EDGES + e]], 1);
}

// single-block exclusive scan over g_count -> g_off (and cursor in g_count)
__global__ void scan_kernel() {
    __shared__ int warpsum[32];
    __shared__ int warpexcl[32];
    __shared__ int sh_total;
    __shared__ int sh_running;
    int tid = threadIdx.x, lane = tid & 31, wid = tid >> 5;
    if (tid == 0) sh_running = 0;
    __syncthreads();
    for (int base = 0; base < N_NODES; base += 1024) {
        int i = base + tid;
        int v = (i < N_NODES) ? g_count[i] : 0;
        int s = v;
#pragma unroll
        for (int d = 1; d < 32; d <<= 1) {
            int t = __shfl_up_sync(0xffffffffu, s, d);
            if (lane >= d) s += t;
        }
        if (lane == 31) warpsum[wid] = s;
        __syncthreads();
        if (wid == 0) {
            int w = warpsum[lane];
            int sw = w;
#pragma unroll
            for (int d = 1; d < 32; d <<= 1) {
                int t = __shfl_up_sync(0xffffffffu, sw, d);
                if (lane >= d) sw += t;
            }
            warpexcl[lane] = sw - w;
            if (lane == 31) sh_total = sw;
        }
        __syncthreads();
        int excl = (s - v) + warpexcl[wid] + sh_running;
        if (i < N_NODES) { g_off[i] = excl; g_count[i] = excl; }
        __syncthreads();
        if (tid == 0) sh_running += sh_total;
        __syncthreads();
    }
    if (tid == 0) g_off[N_NODES] = sh_running;  // == N_EDGES
}

__global__ void fill_kernel(const int* __restrict__ ei) {
    int e = blockIdx.x * blockDim.x + threadIdx.x;
    if (e >= N_EDGES) return;
    int dst = ei[N_EDGES + e];
    int pos = atomicAdd(&g_count[dst], 1);
    g_csr_src[pos] = ei[e];
}

// ---------------- per-layer: CSR gather (scatter-mean without atomics) ----------------
// 16 threads per node, each handles 4 features via float4. 256 thr/block = 16 nodes.
__global__ void gather_kernel(const float* __restrict__ xin) {
    int t = blockIdx.x * 256 + threadIdx.x;
    int node = t >> 4;
    int q = t & 15;
    int start = __ldg(&g_off[node]);
    int end = __ldg(&g_off[node + 1]);
    const float4* x4 = (const float4*)xin;
    float4 acc = make_float4(0.f, 0.f, 0.f, 0.f);
    for (int i = start; i < end; i++) {
        int src = __ldg(&g_csr_src[i]);
        float4 v = __ldg(&x4[src * 16 + q]);
        acc.x += v.x; acc.y += v.y; acc.z += v.z; acc.w += v.w;
    }
    int deg = end - start;
    float invd = 1.0f / (float)(deg > 0 ? deg : 1);
    acc.x *= invd; acc.y *= invd; acc.z *= invd; acc.w *= invd;
    ((float4*)g_agg)[node * 16 + q] = acc;
}

// ---------------- node update: y = relu(agg@Wl + bl + x@Wr) ----------------
// Block: 256 threads = 4 groups x 64 features; each group computes 4 nodes.
// W staged in shared; rows staged in shared, read as broadcast float4.
__global__ void __launch_bounds__(256) node_update_kernel(
    const float* __restrict__ xin,
    const float* __restrict__ Wl,
    const float* __restrict__ bl,
    const float* __restrict__ Wr,
    float* __restrict__ xout) {
    __shared__ float4 sWl4[1024];   // 64x64 floats
    __shared__ float4 sWr4[1024];
    __shared__ float4 sAgg4[256];   // 16 nodes x 64 floats
    __shared__ float4 sX4[256];

    int tid = threadIdx.x;
    int node0 = blockIdx.x * 16;

    const float4* Wl4 = (const float4*)Wl;
    const float4* Wr4 = (const float4*)Wr;
#pragma unroll
    for (int i = tid; i < 1024; i += 256) {
        sWl4[i] = Wl4[i];
        sWr4[i] = Wr4[i];
    }
    {
        int n = tid >> 4, q = tid & 15;
        sAgg4[tid] = ((const float4*)g_agg)[(node0 + n) * 16 + q];
        sX4[tid]   = ((const float4*)xin)[(node0 + n) * 16 + q];
    }
    __syncthreads();

    const float* sWl = (const float*)sWl4;
    const float* sWr = (const float*)sWr4;
    int f = tid & 63;
    int grp = tid >> 6;  // 0..3 -> local nodes grp*4 .. grp*4+3

    const float4* a0 = &sAgg4[(grp * 4 + 0) * 16];
    const float4* a1 = &sAgg4[(grp * 4 + 1) * 16];
    const float4* a2 = &sAgg4[(grp * 4 + 2) * 16];
    const float4* a3 = &sAgg4[(grp * 4 + 3) * 16];
    const float4* x0 = &sX4[(grp * 4 + 0) * 16];
    const float4* x1 = &sX4[(grp * 4 + 1) * 16];
    const float4* x2 = &sX4[(grp * 4 + 2) * 16];
    const float4* x3 = &sX4[(grp * 4 + 3) * 16];

    float l0 = 0.f, l1 = 0.f, l2 = 0.f, l3 = 0.f;
    float r0 = 0.f, r1 = 0.f, r2 = 0.f, r3 = 0.f;

#pragma unroll
    for (int k4 = 0; k4 < 16; k4++) {
        float4 av0 = a0[k4], av1 = a1[k4], av2 = a2[k4], av3 = a3[k4];
        float4 xv0 = x0[k4], xv1 = x1[k4], xv2 = x2[k4], xv3 = x3[k4];
#pragma unroll
        for (int kk = 0; kk < 4; kk++) {
            int k = k4 * 4 + kk;
            float wl = sWl[k * 64 + f];
            float wr = sWr[k * 64 + f];
            float a0s = (&av0.x)[kk], a1s = (&av1.x)[kk], a2s = (&av2.x)[kk], a3s = (&av3.x)[kk];
            float x0s = (&xv0.x)[kk], x1s = (&xv1.x)[kk], x2s = (&xv2.x)[kk], x3s = (&xv3.x)[kk];
            l0 = fmaf(a0s, wl, l0); r0 = fmaf(x0s, wr, r0);
            l1 = fmaf(a1s, wl, l1); r1 = fmaf(x1s, wr, r1);
            l2 = fmaf(a2s, wl, l2); r2 = fmaf(x2s, wr, r2);
            l3 = fmaf(a3s, wl, l3); r3 = fmaf(x3s, wr, r3);
        }
    }

    float bias = __ldg(&bl[f]);
    float y0 = l0 + bias + r0;
    float y1 = l1 + bias + r1;
    float y2 = l2 + bias + r2;
    float y3 = l3 + bias + r3;
    int base = (node0 + grp * 4) * 64 + f;
    xout[base          ] = y0 > 0.f ? y0 : 0.f;
    xout[base + 64     ] = y1 > 0.f ? y1 : 0.f;
    xout[base + 128    ] = y2 > 0.f ? y2 : 0.f;
    xout[base + 192    ] = y3 > 0.f ? y3 : 0.f;
}

// ---------------- output projection ----------------
__global__ void out_kernel(const float* __restrict__ xin,
                           const float* __restrict__ Wout,
                           const float* __restrict__ bout,
                           float* __restrict__ out) {
    int tid = blockIdx.x * blockDim.x + threadIdx.x;
    int n = tid >> 4;
    int o = tid & 15;
    const float4* xn = (const float4*)&xin[n * HIDDEN];
    float acc = __ldg(&bout[o]);
#pragma unroll
    for (int k4 = 0; k4 < 16; k4++) {
        float4 xv = __ldg(&xn[k4]);
        acc = fmaf(xv.x, __ldg(&Wout[(k4 * 4 + 0) * OUT_DIM + o]), acc);
        acc = fmaf(xv.y, __ldg(&Wout[(k4 * 4 + 1) * OUT_DIM + o]), acc);
        acc = fmaf(xv.z, __ldg(&Wout[(k4 * 4 + 2) * OUT_DIM + o]), acc);
        acc = fmaf(xv.w, __ldg(&Wout[(k4 * 4 + 3) * OUT_DIM + o]), acc);
    }
    out[tid] = acc;
}

extern "C" void kernel_launch(void* const* d_in, const int* in_sizes, int n_in,
                              void* d_out, int out_size) {
    const float* x = (const float*)d_in[0];
    const int* ei = (const int*)d_in[1];
    const float* Wl = (const float*)d_in[2];
    const float* bl = (const float*)d_in[3];
    const float* Wr = (const float*)d_in[4];
    const float* Wout = (const float*)d_in[5];
    const float* bout = (const float*)d_in[6];
    float* out = (float*)d_out;

    const int TPB = 256;
    const int edge_blocks = (N_EDGES + TPB - 1) / TPB;        // 3125
    const int node16_blocks = N_NODES / 16;                    // 3125 (exact)
    const int cnt_blocks = (N_NODES + TPB - 1) / TPB;          // 196
    const int out_blocks = (N_NODES * OUT_DIM) / TPB;          // 3125 (exact)

    // CSR build
    zero_count_kernel<<<cnt_blocks, TPB>>>();
    hist_kernel<<<edge_blocks, TPB>>>(ei);
    scan_kernel<<<1, 1024>>>();
    fill_kernel<<<edge_blocks, TPB>>>(ei);

    // layer 0: x -> g_h0
    gather_kernel<<<node16_blocks, TPB>>>(x);
    node_update_kernel<<<node16_blocks, TPB>>>(x, Wl, bl, Wr, g_h0);

    // layer 1: g_h0 -> g_h1
    gather_kernel<<<node16_blocks, TPB>>>(g_h0);
    node_update_kernel<<<node16_blocks, TPB>>>(
        g_h0, Wl + HIDDEN * HIDDEN, bl + HIDDEN, Wr + HIDDEN * HIDDEN, g_h1);

    // layer 2: g_h1 -> g_h0
    gather_kernel<<<node16_blocks, TPB>>>(g_h1);
    node_update_kernel<<<node16_blocks, TPB>>>(
        g_h1, Wl + 2 * HIDDEN * HIDDEN, bl + 2 * HIDDEN, Wr + 2 * HIDDEN * HIDDEN, g_h0);

    // output projection
    out_kernel<<<out_blocks, TPB>>>(g_h0, Wout, bout, out);
}

// round 4
// speedup vs baseline: 1.0998x; 1.0554x over previous
#include <cuda_runtime.h>

#define N_NODES 50000
#define N_EDGES 800000
#define HIDDEN 64
#define OUT_DIM 16

// ---------------- device scratch (no allocs allowed) ----------------
__device__ int g_count[N_NODES];        // static zero-init; re-zeroed by layer-1 each replay
__device__ int g_off[N_NODES + 1];      // CSR row offsets
__device__ int g_csr[N_EDGES];          // CSR src indices
__device__ __align__(16) float g_h0[N_NODES * HIDDEN];
__device__ __align__(16) float g_h1[N_NODES * HIDDEN];

// ---------------- CSR: histogram ----------------
__global__ void hist_kernel(const int* __restrict__ ei) {
    int e = blockIdx.x * blockDim.x + threadIdx.x;
    if (e >= N_EDGES) return;
    atomicAdd(&g_count[ei[N_EDGES + e]], 1);
}

// ---------------- CSR: parallel exclusive scan (1 block, 1024 thr, 49 elems each) ----
__global__ void scan_kernel() {
    const int PER = 49;  // 1024*49 = 50176 >= 50000
    __shared__ int wsum[32];
    __shared__ int wexcl[32];
    int t = threadIdx.x, lane = t & 31, w = t >> 5;
    int base = t * PER;

    int sum = 0;
#pragma unroll
    for (int i = 0; i < PER; i++) {
        int idx = base + i;
        if (idx < N_NODES) sum += g_count[idx];
    }
    // exclusive scan of per-thread sums
    int s = sum;
#pragma unroll
    for (int d = 1; d < 32; d <<= 1) {
        int tv = __shfl_up_sync(0xffffffffu, s, d);
        if (lane >= d) s += tv;
    }
    if (lane == 31) wsum[w] = s;
    __syncthreads();
    if (w == 0) {
        int v = wsum[lane];
        int sv = v;
#pragma unroll
        for (int d = 1; d < 32; d <<= 1) {
            int tv = __shfl_up_sync(0xffffffffu, sv, d);
            if (lane >= d) sv += tv;
        }
        wexcl[lane] = sv - v;
    }
    __syncthreads();
    int excl = (s - sum) + wexcl[w];
#pragma unroll
    for (int i = 0; i < PER; i++) {
        int idx = base + i;
        if (idx < N_NODES) {
            int v = g_count[idx];
            g_off[idx] = excl;
            g_count[idx] = excl;  // cursor for fill
            excl += v;
        }
    }
    if (t == 1023) g_off[N_NODES] = excl;  // == N_EDGES (this thread's range is all OOB)
}

// ---------------- CSR: fill ----------------
__global__ void fill_kernel(const int* __restrict__ ei) {
    int e = blockIdx.x * blockDim.x + threadIdx.x;
    if (e >= N_EDGES) return;
    int dst = ei[N_EDGES + e];
    int pos = atomicAdd(&g_count[dst], 1);
    g_csr[pos] = ei[e];
}

// ---------------- fused layer: gather-mean + (agg@Wl + bl + x@Wr) + ReLU ----------------
// Block = 16 nodes, 256 threads.
__global__ void __launch_bounds__(256) layer_kernel(
    const float* __restrict__ xin,
    const float* __restrict__ Wl,
    const float* __restrict__ bl,
    const float* __restrict__ Wr,
    float* __restrict__ xout,
    int zero_counts) {
    __shared__ float sW[2 * 4096];   // Wl | Wr  (32 KB)
    __shared__ float4 sAgg[256];     // 16 nodes x 64 floats
    __shared__ float4 sX[256];

    int tid = threadIdx.x;
    int node0 = blockIdx.x * 16;

    // stage weights
    {
        const float4* Wl4 = (const float4*)Wl;
        const float4* Wr4 = (const float4*)Wr;
        float4* sW4 = (float4*)sW;
#pragma unroll
        for (int i = tid; i < 1024; i += 256) {
            sW4[i] = __ldg(&Wl4[i]);
            sW4[1024 + i] = __ldg(&Wr4[i]);
        }
    }
    // re-zero histogram for next replay (only in layer-1 launch)
    if (zero_counts && blockIdx.x < 196) {
        int i = blockIdx.x * 256 + tid;
        if (i < N_NODES) g_count[i] = 0;
    }

    // gather-mean with unroll-by-4 (high MLP)
    int ln = tid >> 4, q = tid & 15;
    int node = node0 + ln;
    int s = __ldg(&g_off[node]);
    int e = __ldg(&g_off[node + 1]);
    const float4* x4 = (const float4*)xin;
    float4 acc = make_float4(0.f, 0.f, 0.f, 0.f);
    int i = s;
    for (; i + 4 <= e; i += 4) {
        int s0 = __ldg(&g_csr[i]);
        int s1 = __ldg(&g_csr[i + 1]);
        int s2 = __ldg(&g_csr[i + 2]);
        int s3 = __ldg(&g_csr[i + 3]);
        float4 v0 = __ldg(&x4[s0 * 16 + q]);
        float4 v1 = __ldg(&x4[s1 * 16 + q]);
        float4 v2 = __ldg(&x4[s2 * 16 + q]);
        float4 v3 = __ldg(&x4[s3 * 16 + q]);
        acc.x += (v0.x + v1.x) + (v2.x + v3.x);
        acc.y += (v0.y + v1.y) + (v2.y + v3.y);
        acc.z += (v0.z + v1.z) + (v2.z + v3.z);
        acc.w += (v0.w + v1.w) + (v2.w + v3.w);
    }
    for (; i < e; i++) {
        int s0 = __ldg(&g_csr[i]);
        float4 v = __ldg(&x4[s0 * 16 + q]);
        acc.x += v.x; acc.y += v.y; acc.z += v.z; acc.w += v.w;
    }
    int deg = e - s;
    float invd = 1.0f / (float)(deg > 0 ? deg : 1);
    acc.x *= invd; acc.y *= invd; acc.z *= invd; acc.w *= invd;
    sAgg[ln * 16 + q] = acc;
    sX[ln * 16 + q] = __ldg(&x4[node * 16 + q]);
    __syncthreads();

    // GEMM: 4 groups x 64 features, 4 nodes per group
    const float* sWl = sW;
    const float* sWr = sW + 4096;
    int f = tid & 63;
    int grp = tid >> 6;

    const float4* a0 = &sAgg[(grp * 4 + 0) * 16];
    const float4* a1 = &sAgg[(grp * 4 + 1) * 16];
    const float4* a2 = &sAgg[(grp * 4 + 2) * 16];
    const float4* a3 = &sAgg[(grp * 4 + 3) * 16];
    const float4* x0 = &sX[(grp * 4 + 0) * 16];
    const float4* x1 = &sX[(grp * 4 + 1) * 16];
    const float4* x2 = &sX[(grp * 4 + 2) * 16];
    const float4* x3 = &sX[(grp * 4 + 3) * 16];

    float l0 = 0.f, l1 = 0.f, l2 = 0.f, l3 = 0.f;
    float r0 = 0.f, r1 = 0.f, r2 = 0.f, r3 = 0.f;
#pragma unroll
    for (int k4 = 0; k4 < 16; k4++) {
        float4 av0 = a0[k4], av1 = a1[k4], av2 = a2[k4], av3 = a3[k4];
        float4 xv0 = x0[k4], xv1 = x1[k4], xv2 = x2[k4], xv3 = x3[k4];
#pragma unroll
        for (int kk = 0; kk < 4; kk++) {
            int k = k4 * 4 + kk;
            float wl = sWl[k * 64 + f];
            float wr = sWr[k * 64 + f];
            l0 = fmaf((&av0.x)[kk], wl, l0); r0 = fmaf((&xv0.x)[kk], wr, r0);
            l1 = fmaf((&av1.x)[kk], wl, l1); r1 = fmaf((&xv1.x)[kk], wr, r1);
            l2 = fmaf((&av2.x)[kk], wl, l2); r2 = fmaf((&xv2.x)[kk], wr, r2);
            l3 = fmaf((&av3.x)[kk], wl, l3); r3 = fmaf((&xv3.x)[kk], wr, r3);
        }
    }
    float bias = __ldg(&bl[f]);
    float y0 = l0 + bias + r0;
    float y1 = l1 + bias + r1;
    float y2 = l2 + bias + r2;
    float y3 = l3 + bias + r3;
    int base = (node0 + grp * 4) * 64 + f;
    xout[base      ] = y0 > 0.f ? y0 : 0.f;
    xout[base + 64 ] = y1 > 0.f ? y1 : 0.f;
    xout[base + 128] = y2 > 0.f ? y2 : 0.f;
    xout[base + 192] = y3 > 0.f ? y3 : 0.f;
}

// ---------------- fused layer 3 + output projection ----------------
__global__ void __launch_bounds__(256) layer3_out_kernel(
    const float* __restrict__ xin,
    const float* __restrict__ Wl,
    const float* __restrict__ bl,
    const float* __restrict__ Wr,
    const float* __restrict__ Wout,
    const float* __restrict__ bout,
    float* __restrict__ out) {
    __shared__ float sW[2 * 4096];
    __shared__ float sWout[HIDDEN * OUT_DIM];  // 4KB
    __shared__ float4 sAgg[256];
    __shared__ float4 sX[256];

    int tid = threadIdx.x;
    int node0 = blockIdx.x * 16;

    {
        const float4* Wl4 = (const float4*)Wl;
        const float4* Wr4 = (const float4*)Wr;
        float4* sW4 = (float4*)sW;
#pragma unroll
        for (int i = tid; i < 1024; i += 256) {
            sW4[i] = __ldg(&Wl4[i]);
            sW4[1024 + i] = __ldg(&Wr4[i]);
        }
        const float4* Wo4 = (const float4*)Wout;
        float4* sWo4 = (float4*)sWout;
        if (tid < 256) sWo4[tid] = __ldg(&Wo4[tid]);
    }

    int ln = tid >> 4, q = tid & 15;
    int node = node0 + ln;
    int s = __ldg(&g_off[node]);
    int e = __ldg(&g_off[node + 1]);
    const float4* x4 = (const float4*)xin;
    float4 acc = make_float4(0.f, 0.f, 0.f, 0.f);
    int i = s;
    for (; i + 4 <= e; i += 4) {
        int s0 = __ldg(&g_csr[i]);
        int s1 = __ldg(&g_csr[i + 1]);
        int s2 = __ldg(&g_csr[i + 2]);
        int s3 = __ldg(&g_csr[i + 3]);
        float4 v0 = __ldg(&x4[s0 * 16 + q]);
        float4 v1 = __ldg(&x4[s1 * 16 + q]);
        float4 v2 = __ldg(&x4[s2 * 16 + q]);
        float4 v3 = __ldg(&x4[s3 * 16 + q]);
        acc.x += (v0.x + v1.x) + (v2.x + v3.x);
        acc.y += (v0.y + v1.y) + (v2.y + v3.y);
        acc.z += (v0.z + v1.z) + (v2.z + v3.z);
        acc.w += (v0.w + v1.w) + (v2.w + v3.w);
    }
    for (; i < e; i++) {
        int s0 = __ldg(&g_csr[i]);
        float4 v = __ldg(&x4[s0 * 16 + q]);
        acc.x += v.x; acc.y += v.y; acc.z += v.z; acc.w += v.w;
    }
    int deg = e - s;
    float invd = 1.0f / (float)(deg > 0 ? deg : 1);
    acc.x *= invd; acc.y *= invd; acc.z *= invd; acc.w *= invd;
    sAgg[ln * 16 + q] = acc;
    sX[ln * 16 + q] = __ldg(&x4[node * 16 + q]);
    __syncthreads();

    const float* sWl = sW;
    const float* sWr = sW + 4096;
    int f = tid & 63;
    int grp = tid >> 6;

    const float4* a0 = &sAgg[(grp * 4 + 0) * 16];
    const float4* a1 = &sAgg[(grp * 4 + 1) * 16];
    const float4* a2 = &sAgg[(grp * 4 + 2) * 16];
    const float4* a3 = &sAgg[(grp * 4 + 3) * 16];
    const float4* x0 = &sX[(grp * 4 + 0) * 16];
    const float4* x1 = &sX[(grp * 4 + 1) * 16];
    const float4* x2 = &sX[(grp * 4 + 2) * 16];
    const float4* x3 = &sX[(grp * 4 + 3) * 16];

    float l0 = 0.f, l1 = 0.f, l2 = 0.f, l3 = 0.f;
    float r0 = 0.f, r1 = 0.f, r2 = 0.f, r3 = 0.f;
#pragma unroll
    for (int k4 = 0; k4 < 16; k4++) {
        float4 av0 = a0[k4], av1 = a1[k4], av2 = a2[k4], av3 = a3[k4];
        float4 xv0 = x0[k4], xv1 = x1[k4], xv2 = x2[k4], xv3 = x3[k4];
#pragma unroll
        for (int kk = 0; kk < 4; kk++) {
            int k = k4 * 4 + kk;
            float wl = sWl[k * 64 + f];
            float wr = sWr[k * 64 + f];
            l0 = fmaf((&av0.x)[kk], wl, l0); r0 = fmaf((&xv0.x)[kk], wr, r0);
            l1 = fmaf((&av1.x)[kk], wl, l1); r1 = fmaf((&xv1.x)[kk], wr, r1);
            l2 = fmaf((&av2.x)[kk], wl, l2); r2 = fmaf((&xv2.x)[kk], wr, r2);
            l3 = fmaf((&av3.x)[kk], wl, l3); r3 = fmaf((&xv3.x)[kk], wr, r3);
        }
    }
    float bias = __ldg(&bl[f]);
    float y0 = l0 + bias + r0; y0 = y0 > 0.f ? y0 : 0.f;
    float y1 = l1 + bias + r1; y1 = y1 > 0.f ? y1 : 0.f;
    float y2 = l2 + bias + r2; y2 = y2 > 0.f ? y2 : 0.f;
    float y3 = l3 + bias + r3; y3 = y3 > 0.f ? y3 : 0.f;

    // stash relu'd hidden into smem (reuse sAgg as [16][64] floats)
    __syncthreads();  // all GEMM reads of sAgg/sX complete
    float* sY = (float*)sAgg;
    int nb = grp * 4;
    sY[(nb + 0) * 64 + f] = y0;
    sY[(nb + 1) * 64 + f] = y1;
    sY[(nb + 2) * 64 + f] = y2;
    sY[(nb + 3) * 64 + f] = y3;
    __syncthreads();

    // output projection: thread = (local node, out col)
    int n = tid >> 4;
    int o = tid & 15;
    const float4* yv4 = (const float4*)&sY[n * 64];
    float oacc = __ldg(&bout[o]);
#pragma unroll
    for (int k4 = 0; k4 < 16; k4++) {
        float4 yv = yv4[k4];
        oacc = fmaf(yv.x, sWout[(k4 * 4 + 0) * OUT_DIM + o], oacc);
        oacc = fmaf(yv.y, sWout[(k4 * 4 + 1) * OUT_DIM + o], oacc);
        oacc = fmaf(yv.z, sWout[(k4 * 4 + 2) * OUT_DIM + o], oacc);
        oacc = fmaf(yv.w, sWout[(k4 * 4 + 3) * OUT_DIM + o], oacc);
    }
    out[(node0 + n) * OUT_DIM + o] = oacc;
}

extern "C" void kernel_launch(void* const* d_in, const int* in_sizes, int n_in,
                              void* d_out, int out_size) {
    const float* x = (const float*)d_in[0];
    const int* ei = (const int*)d_in[1];
    const float* Wl = (const float*)d_in[2];
    const float* bl = (const float*)d_in[3];
    const float* Wr = (const float*)d_in[4];
    const float* Wout = (const float*)d_in[5];
    const float* bout = (const float*)d_in[6];
    float* out = (float*)d_out;

    const int TPB = 256;
    const int edge_blocks = (N_EDGES + TPB - 1) / TPB;   // 3125
    const int node16_blocks = N_NODES / 16;              // 3125 (exact)

    // CSR build (g_count is zero: static init on first call, re-zeroed by layer-1 after)
    hist_kernel<<<edge_blocks, TPB>>>(ei);               // launch 1
    scan_kernel<<<1, 1024>>>();                          // launch 2
    fill_kernel<<<edge_blocks, TPB>>>(ei);               // launch 3

    // layer 1 (launch 4 -> profiled slot); also re-zeroes g_count for next replay
    layer_kernel<<<node16_blocks, TPB>>>(x, Wl, bl, Wr, g_h0, 1);
    // layer 2
    layer_kernel<<<node16_blocks, TPB>>>(
        g_h0, Wl + HIDDEN * HIDDEN, bl + HIDDEN, Wr + HIDDEN * HIDDEN, g_h1, 0);
    // layer 3 + output projection
    layer3_out_kernel<<<node16_blocks, TPB>>>(
        g_h1, Wl + 2 * HIDDEN * HIDDEN, bl + 2 * HIDDEN, Wr + 2 * HIDDEN * HIDDEN,
        Wout, bout, out);
}

// round 5
// speedup vs baseline: 1.1000x; 1.0001x over previous
#include <cuda_runtime.h>

#define N_NODES 50000
#define N_EDGES 800000
#define HIDDEN 64
#define OUT_DIM 16

// ---------------- device scratch (no allocs allowed) ----------------
__device__ int g_count[N_NODES];        // zero on load; re-zeroed by layer-1 each replay
__device__ int g_off[N_NODES + 1];
__device__ int g_csr[N_EDGES];
__device__ __align__(16) float g_h0[N_NODES * HIDDEN];
__device__ __align__(16) float g_h1[N_NODES * HIDDEN];

// ---------------- CSR: histogram (int4-vectorized) ----------------
__global__ void hist_kernel(const int* __restrict__ ei) {
    int t = blockIdx.x * blockDim.x + threadIdx.x;
    const int4* dst4 = (const int4*)(ei + N_EDGES);
    if (t < N_EDGES / 4) {
        int4 d = __ldg(&dst4[t]);
        atomicAdd(&g_count[d.x], 1);
        atomicAdd(&g_count[d.y], 1);
        atomicAdd(&g_count[d.z], 1);
        atomicAdd(&g_count[d.w], 1);
    }
}

// ---------------- CSR: exclusive scan (1 block, 1024 thr, 49 each) ----------------
__global__ void scan_kernel() {
    const int PER = 49;
    __shared__ int wsum[32];
    __shared__ int wexcl[32];
    int t = threadIdx.x, lane = t & 31, w = t >> 5;
    int base = t * PER;

    int sum = 0;
#pragma unroll
    for (int i = 0; i < PER; i++) {
        int idx = base + i;
        if (idx < N_NODES) sum += g_count[idx];
    }
    int s = sum;
#pragma unroll
    for (int d = 1; d < 32; d <<= 1) {
        int tv = __shfl_up_sync(0xffffffffu, s, d);
        if (lane >= d) s += tv;
    }
    if (lane == 31) wsum[w] = s;
    __syncthreads();
    if (w == 0) {
        int v = wsum[lane];
        int sv = v;
#pragma unroll
        for (int d = 1; d < 32; d <<= 1) {
            int tv = __shfl_up_sync(0xffffffffu, sv, d);
            if (lane >= d) sv += tv;
        }
        wexcl[lane] = sv - v;
    }
    __syncthreads();
    int excl = (s - sum) + wexcl[w];
#pragma unroll
    for (int i = 0; i < PER; i++) {
        int idx = base + i;
        if (idx < N_NODES) {
            int v = g_count[idx];
            g_off[idx] = excl;
            g_count[idx] = excl;
            excl += v;
        }
    }
    if (t == 1023) g_off[N_NODES] = excl;
}

// ---------------- CSR: fill (int4-vectorized) ----------------
__global__ void fill_kernel(const int* __restrict__ ei) {
    int t = blockIdx.x * blockDim.x + threadIdx.x;
    const int4* src4 = (const int4*)ei;
    const int4* dst4 = (const int4*)(ei + N_EDGES);
    if (t < N_EDGES / 4) {
        int4 sv = __ldg(&src4[t]);
        int4 d = __ldg(&dst4[t]);
        g_csr[atomicAdd(&g_count[d.x], 1)] = sv.x;
        g_csr[atomicAdd(&g_count[d.y], 1)] = sv.y;
        g_csr[atomicAdd(&g_count[d.z], 1)] = sv.z;
        g_csr[atomicAdd(&g_count[d.w], 1)] = sv.w;
    }
}

// ---------------- pipelined gather-mean into smem ----------------
// 16 threads per node; prefetch next chunk's indices before consuming current data.
__device__ __forceinline__ float4 gather_mean(const float4* __restrict__ x4,
                                              int node, int q) {
    int s = __ldg(&g_off[node]);
    int e = __ldg(&g_off[node + 1]);
    float4 acc = make_float4(0.f, 0.f, 0.f, 0.f);
    int i = s;
    int i0 = 0, i1 = 0, i2 = 0, i3 = 0;
    if (i + 4 <= e) {
        i0 = __ldg(&g_csr[i]);
        i1 = __ldg(&g_csr[i + 1]);
        i2 = __ldg(&g_csr[i + 2]);
        i3 = __ldg(&g_csr[i + 3]);
    }
    while (i + 4 <= e) {
        float4 v0 = __ldg(&x4[i0 * 16 + q]);
        float4 v1 = __ldg(&x4[i1 * 16 + q]);
        float4 v2 = __ldg(&x4[i2 * 16 + q]);
        float4 v3 = __ldg(&x4[i3 * 16 + q]);
        i += 4;
        if (i + 4 <= e) {  // prefetch next chunk's indices while v* are in flight
            i0 = __ldg(&g_csr[i]);
            i1 = __ldg(&g_csr[i + 1]);
            i2 = __ldg(&g_csr[i + 2]);
            i3 = __ldg(&g_csr[i + 3]);
        }
        acc.x += (v0.x + v1.x) + (v2.x + v3.x);
        acc.y += (v0.y + v1.y) + (v2.y + v3.y);
        acc.z += (v0.z + v1.z) + (v2.z + v3.z);
        acc.w += (v0.w + v1.w) + (v2.w + v3.w);
    }
    for (; i < e; i++) {
        int s0 = __ldg(&g_csr[i]);
        float4 v = __ldg(&x4[s0 * 16 + q]);
        acc.x += v.x; acc.y += v.y; acc.z += v.z; acc.w += v.w;
    }
    int deg = e - s;
    float invd = 1.0f / (float)(deg > 0 ? deg : 1);
    acc.x *= invd; acc.y *= invd; acc.z *= invd; acc.w *= invd;
    return acc;
}

// ---------------- fused layer: gather-mean + (agg@Wl + bl + x@Wr) + ReLU ----------------
__global__ void __launch_bounds__(256) layer_kernel(
    const float* __restrict__ xin,
    const float* __restrict__ Wl,
    const float* __restrict__ bl,
    const float* __restrict__ Wr,
    float* __restrict__ xout,
    int zero_counts) {
    __shared__ float sW[2 * 4096];
    __shared__ float4 sAgg[256];
    __shared__ float4 sX[256];

    int tid = threadIdx.x;
    int node0 = blockIdx.x * 16;

    {
        const float4* Wl4 = (const float4*)Wl;
        const float4* Wr4 = (const float4*)Wr;
        float4* sW4 = (float4*)sW;
#pragma unroll
        for (int i = tid; i < 1024; i += 256) {
            sW4[i] = __ldg(&Wl4[i]);
            sW4[1024 + i] = __ldg(&Wr4[i]);
        }
    }
    if (zero_counts && blockIdx.x < 196) {
        int i = blockIdx.x * 256 + tid;
        if (i < N_NODES) g_count[i] = 0;
    }

    int ln = tid >> 4, q = tid & 15;
    int node = node0 + ln;
    const float4* x4 = (const float4*)xin;
    sAgg[ln * 16 + q] = gather_mean(x4, node, q);
    sX[ln * 16 + q] = __ldg(&x4[node * 16 + q]);
    __syncthreads();

    const float* sWl = sW;
    const float* sWr = sW + 4096;
    int f = tid & 63;
    int grp = tid >> 6;

    const float4* a0 = &sAgg[(grp * 4 + 0) * 16];
    const float4* a1 = &sAgg[(grp * 4 + 1) * 16];
    const float4* a2 = &sAgg[(grp * 4 + 2) * 16];
    const float4* a3 = &sAgg[(grp * 4 + 3) * 16];
    const float4* x0 = &sX[(grp * 4 + 0) * 16];
    const float4* x1 = &sX[(grp * 4 + 1) * 16];
    const float4* x2 = &sX[(grp * 4 + 2) * 16];
    const float4* x3 = &sX[(grp * 4 + 3) * 16];

    float l0 = 0.f, l1 = 0.f, l2 = 0.f, l3 = 0.f;
    float r0 = 0.f, r1 = 0.f, r2 = 0.f, r3 = 0.f;
#pragma unroll
    for (int k4 = 0; k4 < 16; k4++) {
        float4 av0 = a0[k4], av1 = a1[k4], av2 = a2[k4], av3 = a3[k4];
        float4 xv0 = x0[k4], xv1 = x1[k4], xv2 = x2[k4], xv3 = x3[k4];
#pragma unroll
        for (int kk = 0; kk < 4; kk++) {
            int k = k4 * 4 + kk;
            float wl = sWl[k * 64 + f];
            float wr = sWr[k * 64 + f];
            l0 = fmaf((&av0.x)[kk], wl, l0); r0 = fmaf((&xv0.x)[kk], wr, r0);
            l1 = fmaf((&av1.x)[kk], wl, l1); r1 = fmaf((&xv1.x)[kk], wr, r1);
            l2 = fmaf((&av2.x)[kk], wl, l2); r2 = fmaf((&xv2.x)[kk], wr, r2);
            l3 = fmaf((&av3.x)[kk], wl, l3); r3 = fmaf((&xv3.x)[kk], wr, r3);
        }
    }
    float bias = __ldg(&bl[f]);
    float y0 = l0 + bias + r0;
    float y1 = l1 + bias + r1;
    float y2 = l2 + bias + r2;
    float y3 = l3 + bias + r3;
    int base = (node0 + grp * 4) * 64 + f;
    xout[base      ] = y0 > 0.f ? y0 : 0.f;
    xout[base + 64 ] = y1 > 0.f ? y1 : 0.f;
    xout[base + 128] = y2 > 0.f ? y2 : 0.f;
    xout[base + 192] = y3 > 0.f ? y3 : 0.f;
}

// ---------------- fused layer 3 + output projection ----------------
__global__ void __launch_bounds__(256) layer3_out_kernel(
    const float* __restrict__ xin,
    const float* __restrict__ Wl,
    const float* __restrict__ bl,
    const float* __restrict__ Wr,
    const float* __restrict__ Wout,
    const float* __restrict__ bout,
    float* __restrict__ out) {
    __shared__ float sW[2 * 4096];
    __shared__ float sWout[HIDDEN * OUT_DIM];
    __shared__ float4 sAgg[256];
    __shared__ float4 sX[256];

    int tid = threadIdx.x;
    int node0 = blockIdx.x * 16;

    {
        const float4* Wl4 = (const float4*)Wl;
        const float4* Wr4 = (const float4*)Wr;
        float4* sW4 = (float4*)sW;
#pragma unroll
        for (int i = tid; i < 1024; i += 256) {
            sW4[i] = __ldg(&Wl4[i]);
            sW4[1024 + i] = __ldg(&Wr4[i]);
        }
        const float4* Wo4 = (const float4*)Wout;
        ((float4*)sWout)[tid] = __ldg(&Wo4[tid]);
    }

    int ln = tid >> 4, q = tid & 15;
    int node = node0 + ln;
    const float4* x4 = (const float4*)xin;
    sAgg[ln * 16 + q] = gather_mean(x4, node, q);
    sX[ln * 16 + q] = __ldg(&x4[node * 16 + q]);
    __syncthreads();

    const float* sWl = sW;
    const float* sWr = sW + 4096;
    int f = tid & 63;
    int grp = tid >> 6;

    const float4* a0 = &sAgg[(grp * 4 + 0) * 16];
    const float4* a1 = &sAgg[(grp * 4 + 1) * 16];
    const float4* a2 = &sAgg[(grp * 4 + 2) * 16];
    const float4* a3 = &sAgg[(grp * 4 + 3) * 16];
    const float4* x0 = &sX[(grp * 4 + 0) * 16];
    const float4* x1 = &sX[(grp * 4 + 1) * 16];
    const float4* x2 = &sX[(grp * 4 + 2) * 16];
    const float4* x3 = &sX[(grp * 4 + 3) * 16];

    float l0 = 0.f, l1 = 0.f, l2 = 0.f, l3 = 0.f;
    float r0 = 0.f, r1 = 0.f, r2 = 0.f, r3 = 0.f;
#pragma unroll
    for (int k4 = 0; k4 < 16; k4++) {
        float4 av0 = a0[k4], av1 = a1[k4], av2 = a2[k4], av3 = a3[k4];
        float4 xv0 = x0[k4], xv1 = x1[k4], xv2 = x2[k4], xv3 = x3[k4];
#pragma unroll
        for (int kk = 0; kk < 4; kk++) {
            int k = k4 * 4 + kk;
            float wl = sWl[k * 64 + f];
            float wr = sWr[k * 64 + f];
            l0 = fmaf((&av0.x)[kk], wl, l0); r0 = fmaf((&xv0.x)[kk], wr, r0);
            l1 = fmaf((&av1.x)[kk], wl, l1); r1 = fmaf((&xv1.x)[kk], wr, r1);
            l2 = fmaf((&av2.x)[kk], wl, l2); r2 = fmaf((&xv2.x)[kk], wr, r2);
            l3 = fmaf((&av3.x)[kk], wl, l3); r3 = fmaf((&xv3.x)[kk], wr, r3);
        }
    }
    float bias = __ldg(&bl[f]);
    float y0 = l0 + bias + r0; y0 = y0 > 0.f ? y0 : 0.f;
    float y1 = l1 + bias + r1; y1 = y1 > 0.f ? y1 : 0.f;
    float y2 = l2 + bias + r2; y2 = y2 > 0.f ? y2 : 0.f;
    float y3 = l3 + bias + r3; y3 = y3 > 0.f ? y3 : 0.f;

    __syncthreads();
    float* sY = (float*)sAgg;
    int nb = grp * 4;
    sY[(nb + 0) * 64 + f] = y0;
    sY[(nb + 1) * 64 + f] = y1;
    sY[(nb + 2) * 64 + f] = y2;
    sY[(nb + 3) * 64 + f] = y3;
    __syncthreads();

    int n = tid >> 4;
    int o = tid & 15;
    const float4* yv4 = (const float4*)&sY[n * 64];
    float oacc = __ldg(&bout[o]);
#pragma unroll
    for (int k4 = 0; k4 < 16; k4++) {
        float4 yv = yv4[k4];
        oacc = fmaf(yv.x, sWout[(k4 * 4 + 0) * OUT_DIM + o], oacc);
        oacc = fmaf(yv.y, sWout[(k4 * 4 + 1) * OUT_DIM + o], oacc);
        oacc = fmaf(yv.z, sWout[(k4 * 4 + 2) * OUT_DIM + o], oacc);
        oacc = fmaf(yv.w, sWout[(k4 * 4 + 3) * OUT_DIM + o], oacc);
    }
    out[(node0 + n) * OUT_DIM + o] = oacc;
}

extern "C" void kernel_launch(void* const* d_in, const int* in_sizes, int n_in,
                              void* d_out, int out_size) {
    const float* x = (const float*)d_in[0];
    const int* ei = (const int*)d_in[1];
    const float* Wl = (const float*)d_in[2];
    const float* bl = (const float*)d_in[3];
    const float* Wr = (const float*)d_in[4];
    const float* Wout = (const float*)d_in[5];
    const float* bout = (const float*)d_in[6];
    float* out = (float*)d_out;

    const int TPB = 256;
    const int e4_blocks = (N_EDGES / 4 + TPB - 1) / TPB;  // 782
    const int node16_blocks = N_NODES / 16;               // 3125

    hist_kernel<<<e4_blocks, TPB>>>(ei);                  // 1
    scan_kernel<<<1, 1024>>>();                           // 2
    fill_kernel<<<e4_blocks, TPB>>>(ei);                  // 3

    layer_kernel<<<node16_blocks, TPB>>>(x, Wl, bl, Wr, g_h0, 1);              // 4 (profiled)
    layer_kernel<<<node16_blocks, TPB>>>(
        g_h0, Wl + HIDDEN * HIDDEN, bl + HIDDEN, Wr + HIDDEN * HIDDEN, g_h1, 0);
    layer3_out_kernel<<<node16_blocks, TPB>>>(
        g_h1, Wl + 2 * HIDDEN * HIDDEN, bl + 2 * HIDDEN, Wr + 2 * HIDDEN * HIDDEN,
        Wout, bout, out);
}

// round 6
// speedup vs baseline: 13.3191x; 12.1086x over previous
#include <cuda_runtime.h>

#define N_NODES 50000
#define N_EDGES 800000
#define HIDDEN 64
#define OUT_DIM 16
#define NBLK 592          // 4 blocks/SM x 148 SMs: guaranteed co-resident
#define TPB 256
#define GSTRIDE (NBLK * TPB)
#define CHUNK 85          // ceil(50000/592)
#define NTILES 3125       // 50000/16

// ---------------- device scratch ----------------
__device__ int g_count[N_NODES];
__device__ int g_off[N_NODES + 1];
__device__ int g_csr[N_EDGES];
__device__ int g_blocksum[NBLK];
__device__ int g_blockoff[NBLK];
__device__ unsigned g_bar_cnt;   // zero-init; returns to 0 after each barrier
__device__ unsigned g_bar_gen;   // monotonically increasing generation
__device__ __align__(16) float g_h0[N_NODES * HIDDEN];
__device__ __align__(16) float g_h1[N_NODES * HIDDEN];

// ---------------- software grid barrier (all NBLK blocks co-resident) ----------------
__device__ __forceinline__ void grid_barrier() {
    __syncthreads();
    if (threadIdx.x == 0) {
        unsigned gen = *((volatile unsigned*)&g_bar_gen);
        __threadfence();
        unsigned a = atomicAdd(&g_bar_cnt, 1u);
        if (a == NBLK - 1) {
            g_bar_cnt = 0;
            __threadfence();
            atomicExch(&g_bar_gen, gen + 1u);
        } else {
            while (*((volatile unsigned*)&g_bar_gen) == gen) { __nanosleep(32); }
        }
        __threadfence();
    }
    __syncthreads();
}

// ---------------- pipelined gather-mean ----------------
__device__ __forceinline__ float4 gather_mean(const float4* __restrict__ x4,
                                              int node, int q) {
    int s = __ldg(&g_off[node]);
    int e = __ldg(&g_off[node + 1]);
    float4 acc = make_float4(0.f, 0.f, 0.f, 0.f);
    int i = s;
    int i0 = 0, i1 = 0, i2 = 0, i3 = 0;
    if (i + 4 <= e) {
        i0 = __ldg(&g_csr[i]);     i1 = __ldg(&g_csr[i + 1]);
        i2 = __ldg(&g_csr[i + 2]); i3 = __ldg(&g_csr[i + 3]);
    }
    while (i + 4 <= e) {
        float4 v0 = __ldg(&x4[i0 * 16 + q]);
        float4 v1 = __ldg(&x4[i1 * 16 + q]);
        float4 v2 = __ldg(&x4[i2 * 16 + q]);
        float4 v3 = __ldg(&x4[i3 * 16 + q]);
        i += 4;
        if (i + 4 <= e) {
            i0 = __ldg(&g_csr[i]);     i1 = __ldg(&g_csr[i + 1]);
            i2 = __ldg(&g_csr[i + 2]); i3 = __ldg(&g_csr[i + 3]);
        }
        acc.x += (v0.x + v1.x) + (v2.x + v3.x);
        acc.y += (v0.y + v1.y) + (v2.y + v3.y);
        acc.z += (v0.z + v1.z) + (v2.z + v3.z);
        acc.w += (v0.w + v1.w) + (v2.w + v3.w);
    }
    for (; i < e; i++) {
        int s0 = __ldg(&g_csr[i]);
        float4 v = __ldg(&x4[s0 * 16 + q]);
        acc.x += v.x; acc.y += v.y; acc.z += v.z; acc.w += v.w;
    }
    int deg = e - s;
    float invd = 1.0f / (float)(deg > 0 ? deg : 1);
    acc.x *= invd; acc.y *= invd; acc.z *= invd; acc.w *= invd;
    return acc;
}

// ---------------- per-tile: gather + dual GEMM + relu -> xout ----------------
__device__ __forceinline__ void do_tile(const float* __restrict__ xin,
                                        const float* sWl, const float* sWr,
                                        const float* __restrict__ bl,
                                        float* __restrict__ xout,
                                        int tile, int tid, float4* sStage) {
    float4* sAgg = sStage;
    float4* sX = sStage + 256;
    int node0 = tile * 16;
    int ln = tid >> 4, q = tid & 15;
    int node = node0 + ln;
    const float4* x4 = (const float4*)xin;
    sAgg[ln * 16 + q] = gather_mean(x4, node, q);
    sX[ln * 16 + q] = __ldg(&x4[node * 16 + q]);
    __syncthreads();

    int f = tid & 63;
    int grp = tid >> 6;
    const float4* a0 = &sAgg[(grp * 4 + 0) * 16];
    const float4* a1 = &sAgg[(grp * 4 + 1) * 16];
    const float4* a2 = &sAgg[(grp * 4 + 2) * 16];
    const float4* a3 = &sAgg[(grp * 4 + 3) * 16];
    const float4* x0 = &sX[(grp * 4 + 0) * 16];
    const float4* x1 = &sX[(grp * 4 + 1) * 16];
    const float4* x2 = &sX[(grp * 4 + 2) * 16];
    const float4* x3 = &sX[(grp * 4 + 3) * 16];

    float l0 = 0.f, l1 = 0.f, l2 = 0.f, l3 = 0.f;
    float r0 = 0.f, r1 = 0.f, r2 = 0.f, r3 = 0.f;
#pragma unroll
    for (int k4 = 0; k4 < 16; k4++) {
        float4 av0 = a0[k4], av1 = a1[k4], av2 = a2[k4], av3 = a3[k4];
        float4 xv0 = x0[k4], xv1 = x1[k4], xv2 = x2[k4], xv3 = x3[k4];
#pragma unroll
        for (int kk = 0; kk < 4; kk++) {
            int k = k4 * 4 + kk;
            float wl = sWl[k * 64 + f];
            float wr = sWr[k * 64 + f];
            l0 = fmaf((&av0.x)[kk], wl, l0); r0 = fmaf((&xv0.x)[kk], wr, r0);
            l1 = fmaf((&av1.x)[kk], wl, l1); r1 = fmaf((&xv1.x)[kk], wr, r1);
            l2 = fmaf((&av2.x)[kk], wl, l2); r2 = fmaf((&xv2.x)[kk], wr, r2);
            l3 = fmaf((&av3.x)[kk], wl, l3); r3 = fmaf((&xv3.x)[kk], wr, r3);
        }
    }
    float bias = __ldg(&bl[f]);
    float y0 = l0 + bias + r0;
    float y1 = l1 + bias + r1;
    float y2 = l2 + bias + r2;
    float y3 = l3 + bias + r3;
    int base = (node0 + grp * 4) * 64 + f;
    xout[base      ] = y0 > 0.f ? y0 : 0.f;
    xout[base + 64 ] = y1 > 0.f ? y1 : 0.f;
    xout[base + 128] = y2 > 0.f ? y2 : 0.f;
    xout[base + 192] = y3 > 0.f ? y3 : 0.f;
    __syncthreads();   // protect sStage before next tile
}

// ---------------- the whole network in one persistent kernel ----------------
__global__ void __launch_bounds__(TPB, 4) fused_kernel(
    const float* __restrict__ x, const int* __restrict__ ei,
    const float* __restrict__ Wl, const float* __restrict__ bl,
    const float* __restrict__ Wr, const float* __restrict__ Wout,
    const float* __restrict__ bout, float* __restrict__ out) {
    __shared__ float sW[2 * 4096];     // 32KB
    __shared__ float4 sStage[512];     // 8KB
    __shared__ float sWout[HIDDEN * OUT_DIM];  // 4KB
    __shared__ int sInts[8];

    int tid = threadIdx.x;
    int b = blockIdx.x;
    int gtid = b * TPB + tid;
    int lane = tid & 31, w = tid >> 5;

    // phase 0: zero counts
    for (int i = gtid; i < N_NODES; i += GSTRIDE) g_count[i] = 0;
    grid_barrier();

    // phase 1: histogram
    {
        const int4* dst4 = (const int4*)(ei + N_EDGES);
        for (int t = gtid; t < N_EDGES / 4; t += GSTRIDE) {
            int4 d = __ldg(&dst4[t]);
            atomicAdd(&g_count[d.x], 1);
            atomicAdd(&g_count[d.y], 1);
            atomicAdd(&g_count[d.z], 1);
            atomicAdd(&g_count[d.w], 1);
        }
    }
    grid_barrier();

    // phase 2a: block-local exclusive scan of CHUNK counts
    {
        int base = b * CHUNK;
        int idx = base + tid;
        int v = (tid < CHUNK && idx < N_NODES) ? g_count[idx] : 0;
        int s = v;
#pragma unroll
        for (int d = 1; d < 32; d <<= 1) {
            int tv = __shfl_up_sync(0xffffffffu, s, d);
            if (lane >= d) s += tv;
        }
        if (lane == 31) sInts[w] = s;
        __syncthreads();
        if (tid == 0) {
            int acc = 0;
#pragma unroll
            for (int k = 0; k < 8; k++) { int t2 = sInts[k]; sInts[k] = acc; acc += t2; }
        }
        __syncthreads();
        int incl = s + sInts[w];
        if (tid < CHUNK && idx < N_NODES) g_off[idx] = incl - v;
        if (tid == TPB - 1) g_blocksum[b] = incl;
    }
    grid_barrier();

    // phase 2b: block 0 exclusive-scans the block sums
    if (b == 0) {
        int base2 = tid * 3;
        int v0 = (base2 + 0 < NBLK) ? g_blocksum[base2 + 0] : 0;
        int v1 = (base2 + 1 < NBLK) ? g_blocksum[base2 + 1] : 0;
        int v2 = (base2 + 2 < NBLK) ? g_blocksum[base2 + 2] : 0;
        int tsum = v0 + v1 + v2;
        int s = tsum;
#pragma unroll
        for (int d = 1; d < 32; d <<= 1) {
            int tv = __shfl_up_sync(0xffffffffu, s, d);
            if (lane >= d) s += tv;
        }
        if (lane == 31) sInts[w] = s;
        __syncthreads();
        if (tid == 0) {
            int acc = 0;
#pragma unroll
            for (int k = 0; k < 8; k++) { int t2 = sInts[k]; sInts[k] = acc; acc += t2; }
        }
        __syncthreads();
        int excl = (s - tsum) + sInts[w];
        if (base2 + 0 < NBLK) { g_blockoff[base2 + 0] = excl; excl += v0; }
        if (base2 + 1 < NBLK) { g_blockoff[base2 + 1] = excl; excl += v1; }
        if (base2 + 2 < NBLK) { g_blockoff[base2 + 2] = excl; excl += v2; }
    }
    grid_barrier();

    // phase 2c: add block offsets; init fill cursors
    {
        int off = g_blockoff[b];
        int idx = b * CHUNK + tid;
        if (tid < CHUNK && idx < N_NODES) {
            int o = g_off[idx] + off;
            g_off[idx] = o;
            g_count[idx] = o;
        }
        if (gtid == 0) g_off[N_NODES] = N_EDGES;
    }
    grid_barrier();

    // phase 3: fill CSR
    {
        const int4* src4 = (const int4*)ei;
        const int4* dst4 = (const int4*)(ei + N_EDGES);
        for (int t = gtid; t < N_EDGES / 4; t += GSTRIDE) {
            int4 sv = __ldg(&src4[t]);
            int4 d = __ldg(&dst4[t]);
            g_csr[atomicAdd(&g_count[d.x], 1)] = sv.x;
            g_csr[atomicAdd(&g_count[d.y], 1)] = sv.y;
            g_csr[atomicAdd(&g_count[d.z], 1)] = sv.z;
            g_csr[atomicAdd(&g_count[d.w], 1)] = sv.w;
        }
    }
    grid_barrier();

    // ---- layer 1: x -> g_h0 ----
    {
        const float4* Wl4 = (const float4*)Wl;
        const float4* Wr4 = (const float4*)Wr;
        float4* sW4 = (float4*)sW;
#pragma unroll
        for (int i = tid; i < 1024; i += TPB) {
            sW4[i] = __ldg(&Wl4[i]);
            sW4[1024 + i] = __ldg(&Wr4[i]);
        }
        __syncthreads();
        for (int tile = b; tile < NTILES; tile += NBLK)
            do_tile(x, sW, sW + 4096, bl, g_h0, tile, tid, sStage);
    }
    grid_barrier();

    // ---- layer 2: g_h0 -> g_h1 ----
    {
        const float4* Wl4 = (const float4*)(Wl + HIDDEN * HIDDEN);
        const float4* Wr4 = (const float4*)(Wr + HIDDEN * HIDDEN);
        float4* sW4 = (float4*)sW;
#pragma unroll
        for (int i = tid; i < 1024; i += TPB) {
            sW4[i] = __ldg(&Wl4[i]);
            sW4[1024 + i] = __ldg(&Wr4[i]);
        }
        __syncthreads();
        for (int tile = b; tile < NTILES; tile += NBLK)
            do_tile(g_h0, sW, sW + 4096, bl + HIDDEN, g_h1, tile, tid, sStage);
    }
    grid_barrier();

    // ---- layer 3 + output projection: g_h1 -> out ----
    {
        const float4* Wl4 = (const float4*)(Wl + 2 * HIDDEN * HIDDEN);
        const float4* Wr4 = (const float4*)(Wr + 2 * HIDDEN * HIDDEN);
        float4* sW4 = (float4*)sW;
#pragma unroll
        for (int i = tid; i < 1024; i += TPB) {
            sW4[i] = __ldg(&Wl4[i]);
            sW4[1024 + i] = __ldg(&Wr4[i]);
        }
        ((float4*)sWout)[tid] = __ldg(&((const float4*)Wout)[tid]);
        __syncthreads();

        const float* sWl = sW;
        const float* sWr = sW + 4096;
        const float* blv = bl + 2 * HIDDEN;
        float4* sAgg = sStage;
        float4* sX = sStage + 256;

        for (int tile = b; tile < NTILES; tile += NBLK) {
            int node0 = tile * 16;
            int ln = tid >> 4, q = tid & 15;
            int node = node0 + ln;
            const float4* x4 = (const float4*)g_h1;
            sAgg[ln * 16 + q] = gather_mean(x4, node, q);
            sX[ln * 16 + q] = __ldg(&x4[node * 16 + q]);
            __syncthreads();

            int f = tid & 63;
            int grp = tid >> 6;
            const float4* a0 = &sAgg[(grp * 4 + 0) * 16];
            const float4* a1 = &sAgg[(grp * 4 + 1) * 16];
            const float4* a2 = &sAgg[(grp * 4 + 2) * 16];
            const float4* a3 = &sAgg[(grp * 4 + 3) * 16];
            const float4* x0 = &sX[(grp * 4 + 0) * 16];
            const float4* x1 = &sX[(grp * 4 + 1) * 16];
            const float4* x2 = &sX[(grp * 4 + 2) * 16];
            const float4* x3 = &sX[(grp * 4 + 3) * 16];

            float l0 = 0.f, l1 = 0.f, l2 = 0.f, l3 = 0.f;
            float r0 = 0.f, r1 = 0.f, r2 = 0.f, r3 = 0.f;
#pragma unroll
            for (int k4 = 0; k4 < 16; k4++) {
                float4 av0 = a0[k4], av1 = a1[k4], av2 = a2[k4], av3 = a3[k4];
                float4 xv0 = x0[k4], xv1 = x1[k4], xv2 = x2[k4], xv3 = x3[k4];
#pragma unroll
                for (int kk = 0; kk < 4; kk++) {
                    int k = k4 * 4 + kk;
                    float wl = sWl[k * 64 + f];
                    float wr = sWr[k * 64 + f];
                    l0 = fmaf((&av0.x)[kk], wl, l0); r0 = fmaf((&xv0.x)[kk], wr, r0);
                    l1 = fmaf((&av1.x)[kk], wl, l1); r1 = fmaf((&xv1.x)[kk], wr, r1);
                    l2 = fmaf((&av2.x)[kk], wl, l2); r2 = fmaf((&xv2.x)[kk], wr, r2);
                    l3 = fmaf((&av3.x)[kk], wl, l3); r3 = fmaf((&xv3.x)[kk], wr, r3);
                }
            }
            float bias = __ldg(&blv[f]);
            float y0 = l0 + bias + r0; y0 = y0 > 0.f ? y0 : 0.f;
            float y1 = l1 + bias + r1; y1 = y1 > 0.f ? y1 : 0.f;
            float y2 = l2 + bias + r2; y2 = y2 > 0.f ? y2 : 0.f;
            float y3 = l3 + bias + r3; y3 = y3 > 0.f ? y3 : 0.f;

            __syncthreads();
            float* sY = (float*)sAgg;
            int nb = grp * 4;
            sY[(nb + 0) * 64 + f] = y0;
            sY[(nb + 1) * 64 + f] = y1;
            sY[(nb + 2) * 64 + f] = y2;
            sY[(nb + 3) * 64 + f] = y3;
            __syncthreads();

            int n = tid >> 4;
            int o = tid & 15;
            const float4* yv4 = (const float4*)&sY[n * 64];
            float oacc = __ldg(&bout[o]);
#pragma unroll
            for (int k4 = 0; k4 < 16; k4++) {
                float4 yv = yv4[k4];
                oacc = fmaf(yv.x, sWout[(k4 * 4 + 0) * OUT_DIM + o], oacc);
                oacc = fmaf(yv.y, sWout[(k4 * 4 + 1) * OUT_DIM + o], oacc);
                oacc = fmaf(yv.z, sWout[(k4 * 4 + 2) * OUT_DIM + o], oacc);
                oacc = fmaf(yv.w, sWout[(k4 * 4 + 3) * OUT_DIM + o], oacc);
            }
            out[(node0 + n) * OUT_DIM + o] = oacc;
            __syncthreads();
        }
    }
}

extern "C" void kernel_launch(void* const* d_in, const int* in_sizes, int n_in,
                              void* d_out, int out_size) {
    const float* x = (const float*)d_in[0];
    const int* ei = (const int*)d_in[1];
    const float* Wl = (const float*)d_in[2];
    const float* bl = (const float*)d_in[3];
    const float* Wr = (const float*)d_in[4];
    const float* Wout = (const float*)d_in[5];
    const float* bout = (const float*)d_in[6];
    float* out = (float*)d_out;

    fused_kernel<<<NBLK, TPB>>>(x, ei, Wl, bl, Wr, Wout, bout, out);
}

// round 7
// speedup vs baseline: 15.4737x; 1.1618x over previous
#include <cuda_runtime.h>

#define N_NODES 50000
#define N_EDGES 800000
#define HIDDEN 64
#define OUT_DIM 16
#define NBLK 444          // 3 blocks/SM x 148 SMs: co-resident (enforced by launch_bounds)
#define TPB 256
#define GSTRIDE (NBLK * TPB)
#define CHUNK 113         // ceil(50000/444)
#define TILE_N 64
#define NTILES 782        // ceil(50000/64)
#define SROW 132          // padded feature row: 128 data + 4 pad (bank-skew)

// ---------------- device scratch ----------------
__device__ int g_count[N_NODES];
__device__ int g_off[N_NODES + 1];
__device__ int g_csr[N_EDGES];
__device__ int g_blocksum[NBLK];
__device__ int g_blockoff[NBLK];
__device__ unsigned g_bar_cnt;   // zero-init; returns to 0 after each barrier
__device__ unsigned g_bar_gen;   // monotonically increasing generation
__device__ __align__(16) float g_h0[N_NODES * HIDDEN];
__device__ __align__(16) float g_h1[N_NODES * HIDDEN];

// ---------------- software grid barrier ----------------
__device__ __forceinline__ void grid_barrier() {
    __syncthreads();
    if (threadIdx.x == 0) {
        unsigned gen = *((volatile unsigned*)&g_bar_gen);
        __threadfence();
        unsigned a = atomicAdd(&g_bar_cnt, 1u);
        if (a == NBLK - 1) {
            g_bar_cnt = 0;
            __threadfence();
            atomicExch(&g_bar_gen, gen + 1u);
        } else {
            while (*((volatile unsigned*)&g_bar_gen) == gen) { __nanosleep(32); }
        }
        __threadfence();
    }
    __syncthreads();
}

__device__ __forceinline__ float4 fma4(float s, float4 w, float4 acc) {
    acc.x = fmaf(s, w.x, acc.x);
    acc.y = fmaf(s, w.y, acc.y);
    acc.z = fmaf(s, w.z, acc.z);
    acc.w = fmaf(s, w.w, acc.w);
    return acc;
}
__device__ __forceinline__ float4 relu4(float4 v) {
    v.x = fmaxf(v.x, 0.f); v.y = fmaxf(v.y, 0.f);
    v.z = fmaxf(v.z, 0.f); v.w = fmaxf(v.w, 0.f);
    return v;
}

// ---------------- pipelined gather-mean (16 threads/node, q = float4 index) ----
__device__ __forceinline__ float4 gather_mean(const float4* __restrict__ x4,
                                              int node, int q) {
    int s = __ldg(&g_off[node]);
    int e = __ldg(&g_off[node + 1]);
    float4 acc = make_float4(0.f, 0.f, 0.f, 0.f);
    int i = s;
    int i0 = 0, i1 = 0, i2 = 0, i3 = 0;
    if (i + 4 <= e) {
        i0 = __ldg(&g_csr[i]);     i1 = __ldg(&g_csr[i + 1]);
        i2 = __ldg(&g_csr[i + 2]); i3 = __ldg(&g_csr[i + 3]);
    }
    while (i + 4 <= e) {
        float4 v0 = __ldg(&x4[i0 * 16 + q]);
        float4 v1 = __ldg(&x4[i1 * 16 + q]);
        float4 v2 = __ldg(&x4[i2 * 16 + q]);
        float4 v3 = __ldg(&x4[i3 * 16 + q]);
        i += 4;
        if (i + 4 <= e) {
            i0 = __ldg(&g_csr[i]);     i1 = __ldg(&g_csr[i + 1]);
            i2 = __ldg(&g_csr[i + 2]); i3 = __ldg(&g_csr[i + 3]);
        }
        acc.x += (v0.x + v1.x) + (v2.x + v3.x);
        acc.y += (v0.y + v1.y) + (v2.y + v3.y);
        acc.z += (v0.z + v1.z) + (v2.z + v3.z);
        acc.w += (v0.w + v1.w) + (v2.w + v3.w);
    }
    for (; i < e; i++) {
        int s0 = __ldg(&g_csr[i]);
        float4 v = __ldg(&x4[s0 * 16 + q]);
        acc.x += v.x; acc.y += v.y; acc.z += v.z; acc.w += v.w;
    }
    int deg = e - s;
    float invd = 1.0f / (float)(deg > 0 ? deg : 1);
    acc.x *= invd; acc.y *= invd; acc.z *= invd; acc.w *= invd;
    return acc;
}

// ---------------- one 64-node tile: gather + combined GEMM (+ optional out proj) ----
template <bool FINAL>
__device__ __forceinline__ void layer_tile(
    const float* __restrict__ xin,
    const float* sW,            // [128][64]: rows 0-63 = Wl, 64-127 = Wr
    const float* sWout,         // [64][16] (FINAL only)
    const float* __restrict__ bl,
    const float* __restrict__ bout,  // FINAL only
    float* __restrict__ dst,    // hidden out (!FINAL) or final out (FINAL)
    int tile, int tid, float* sFeat) {
    int node0 = tile * TILE_N;
    // ---- gather: 4 sub-rounds of 16 nodes; sFeat[n][0:64]=agg, [64:128]=x ----
    {
        int ln = tid >> 4, q = tid & 15;
        const float4* x4 = (const float4*)xin;
#pragma unroll
        for (int sub = 0; sub < 4; sub++) {
            int n = sub * 16 + ln;
            int node = node0 + n;
            float4 agg = make_float4(0.f, 0.f, 0.f, 0.f);
            float4 xv = agg;
            if (node < N_NODES) {
                agg = gather_mean(x4, node, q);
                xv = __ldg(&x4[node * 16 + q]);
            }
            *(float4*)&sFeat[n * SROW + q * 4] = agg;
            *(float4*)&sFeat[n * SROW + 64 + q * 4] = xv;
        }
    }
    __syncthreads();

    // ---- combined GEMM: 4 nodes x 4 features per thread, K=128 ----
    int f0 = (tid & 15) * 4;
    int ngrp = tid >> 4;
    const float* r0 = &sFeat[(ngrp * 4 + 0) * SROW];
    const float* r1 = r0 + SROW;
    const float* r2 = r0 + 2 * SROW;
    const float* r3 = r0 + 3 * SROW;

    float4 bias;
    bias.x = __ldg(&bl[f0]); bias.y = __ldg(&bl[f0 + 1]);
    bias.z = __ldg(&bl[f0 + 2]); bias.w = __ldg(&bl[f0 + 3]);
    float4 acc0 = bias, acc1 = bias, acc2 = bias, acc3 = bias;

#pragma unroll 4
    for (int k4 = 0; k4 < 32; k4++) {
        float4 a0 = *(const float4*)&r0[k4 * 4];
        float4 a1 = *(const float4*)&r1[k4 * 4];
        float4 a2 = *(const float4*)&r2[k4 * 4];
        float4 a3 = *(const float4*)&r3[k4 * 4];
        const float* wb = &sW[k4 * 256 + f0];
        float4 w0 = *(const float4*)&wb[0];
        float4 w1 = *(const float4*)&wb[64];
        float4 w2 = *(const float4*)&wb[128];
        float4 w3 = *(const float4*)&wb[192];
        acc0 = fma4(a0.x, w0, acc0); acc0 = fma4(a0.y, w1, acc0);
        acc0 = fma4(a0.z, w2, acc0); acc0 = fma4(a0.w, w3, acc0);
        acc1 = fma4(a1.x, w0, acc1); acc1 = fma4(a1.y, w1, acc1);
        acc1 = fma4(a1.z, w2, acc1); acc1 = fma4(a1.w, w3, acc1);
        acc2 = fma4(a2.x, w0, acc2); acc2 = fma4(a2.y, w1, acc2);
        acc2 = fma4(a2.z, w2, acc2); acc2 = fma4(a2.w, w3, acc2);
        acc3 = fma4(a3.x, w0, acc3); acc3 = fma4(a3.y, w1, acc3);
        acc3 = fma4(a3.z, w2, acc3); acc3 = fma4(a3.w, w3, acc3);
    }
    acc0 = relu4(acc0); acc1 = relu4(acc1); acc2 = relu4(acc2); acc3 = relu4(acc3);

    int nb = ngrp * 4;
    if (!FINAL) {
        int gn = node0 + nb;
        if (gn + 0 < N_NODES) *(float4*)&dst[(gn + 0) * 64 + f0] = acc0;
        if (gn + 1 < N_NODES) *(float4*)&dst[(gn + 1) * 64 + f0] = acc1;
        if (gn + 2 < N_NODES) *(float4*)&dst[(gn + 2) * 64 + f0] = acc2;
        if (gn + 3 < N_NODES) *(float4*)&dst[(gn + 3) * 64 + f0] = acc3;
        __syncthreads();  // protect sFeat before next tile's gather
    } else {
        __syncthreads();  // all GEMM reads of sFeat complete before overwrite
        *(float4*)&sFeat[(nb + 0) * SROW + f0] = acc0;
        *(float4*)&sFeat[(nb + 1) * SROW + f0] = acc1;
        *(float4*)&sFeat[(nb + 2) * SROW + f0] = acc2;
        *(float4*)&sFeat[(nb + 3) * SROW + f0] = acc3;
        __syncthreads();
        // output projection: thread = (node n = tid>>2, out group o0 = (tid&3)*4)
        int n = tid >> 2;
        int o0 = (tid & 3) * 4;
        float4 oacc;
        oacc.x = __ldg(&bout[o0]); oacc.y = __ldg(&bout[o0 + 1]);
        oacc.z = __ldg(&bout[o0 + 2]); oacc.w = __ldg(&bout[o0 + 3]);
        const float* yr = &sFeat[n * SROW];
#pragma unroll
        for (int k4 = 0; k4 < 16; k4++) {
            float4 yv = *(const float4*)&yr[k4 * 4];
            const float* wb = &sWout[k4 * 64 + o0];
            float4 w0 = *(const float4*)&wb[0];
            float4 w1 = *(const float4*)&wb[16];
            float4 w2 = *(const float4*)&wb[32];
            float4 w3 = *(const float4*)&wb[48];
            oacc = fma4(yv.x, w0, oacc); oacc = fma4(yv.y, w1, oacc);
            oacc = fma4(yv.z, w2, oacc); oacc = fma4(yv.w, w3, oacc);
        }
        int gn = node0 + n;
        if (gn < N_NODES) *(float4*)&dst[gn * OUT_DIM + o0] = oacc;
        __syncthreads();
    }
}

// ---------------- the whole network in one persistent kernel ----------------
__global__ void __launch_bounds__(TPB, 3) fused_kernel(
    const float* __restrict__ x, const int* __restrict__ ei,
    const float* __restrict__ Wl, const float* __restrict__ bl,
    const float* __restrict__ Wr, const float* __restrict__ Wout,
    const float* __restrict__ bout, float* __restrict__ out) {
    extern __shared__ float smem[];
    float* sFeat = smem;                      // 64*132 = 8448 floats (33 KB)
    float* sW = smem + TILE_N * SROW;         // 128*64 = 8192 floats (32 KB)
    float* sWout = sW + 8192;                 // 64*16  = 1024 floats (4 KB)
    int* sInts = (int*)(sWout + 1024);        // 8 ints

    int tid = threadIdx.x;
    int b = blockIdx.x;
    int gtid = b * TPB + tid;
    int lane = tid & 31, w = tid >> 5;

    // phase 0: zero counts
    for (int i = gtid; i < N_NODES; i += GSTRIDE) g_count[i] = 0;
    grid_barrier();

    // phase 1: histogram
    {
        const int4* dst4 = (const int4*)(ei + N_EDGES);
        for (int t = gtid; t < N_EDGES / 4; t += GSTRIDE) {
            int4 d = __ldg(&dst4[t]);
            atomicAdd(&g_count[d.x], 1);
            atomicAdd(&g_count[d.y], 1);
            atomicAdd(&g_count[d.z], 1);
            atomicAdd(&g_count[d.w], 1);
        }
    }
    grid_barrier();

    // phase 2a: block-local exclusive scan of CHUNK counts
    {
        int base = b * CHUNK;
        int idx = base + tid;
        int v = (tid < CHUNK && idx < N_NODES) ? g_count[idx] : 0;
        int s = v;
#pragma unroll
        for (int d = 1; d < 32; d <<= 1) {
            int tv = __shfl_up_sync(0xffffffffu, s, d);
            if (lane >= d) s += tv;
        }
        if (lane == 31) sInts[w] = s;
        __syncthreads();
        if (tid == 0) {
            int acc = 0;
#pragma unroll
            for (int k = 0; k < 8; k++) { int t2 = sInts[k]; sInts[k] = acc; acc += t2; }
        }
        __syncthreads();
        int incl = s + sInts[w];
        if (tid < CHUNK && idx < N_NODES) g_off[idx] = incl - v;
        if (tid == TPB - 1) g_blocksum[b] = incl;
    }
    grid_barrier();

    // phase 2b: block 0 exclusive-scans the NBLK block sums (2 per thread)
    if (b == 0) {
        int base2 = tid * 2;
        int v0 = (base2 + 0 < NBLK) ? g_blocksum[base2 + 0] : 0;
        int v1 = (base2 + 1 < NBLK) ? g_blocksum[base2 + 1] : 0;
        int tsum = v0 + v1;
        int s = tsum;
#pragma unroll
        for (int d = 1; d < 32; d <<= 1) {
            int tv = __shfl_up_sync(0xffffffffu, s, d);
            if (lane >= d) s += tv;
        }
        if (lane == 31) sInts[w] = s;
        __syncthreads();
        if (tid == 0) {
            int acc = 0;
#pragma unroll
            for (int k = 0; k < 8; k++) { int t2 = sInts[k]; sInts[k] = acc; acc += t2; }
        }
        __syncthreads();
        int excl = (s - tsum) + sInts[w];
        if (base2 + 0 < NBLK) g_blockoff[base2 + 0] = excl;
        if (base2 + 1 < NBLK) g_blockoff[base2 + 1] = excl + v0;
    }
    grid_barrier();

    // phase 2c: add block offsets; init fill cursors
    {
        int off = g_blockoff[b];
        int idx = b * CHUNK + tid;
        if (tid < CHUNK && idx < N_NODES) {
            int o = g_off[idx] + off;
            g_off[idx] = o;
            g_count[idx] = o;
        }
        if (gtid == 0) g_off[N_NODES] = N_EDGES;
    }
    grid_barrier();

    // phase 3: fill CSR
    {
        const int4* src4 = (const int4*)ei;
        const int4* dst4 = (const int4*)(ei + N_EDGES);
        for (int t = gtid; t < N_EDGES / 4; t += GSTRIDE) {
            int4 sv = __ldg(&src4[t]);
            int4 d = __ldg(&dst4[t]);
            g_csr[atomicAdd(&g_count[d.x], 1)] = sv.x;
            g_csr[atomicAdd(&g_count[d.y], 1)] = sv.y;
            g_csr[atomicAdd(&g_count[d.z], 1)] = sv.z;
            g_csr[atomicAdd(&g_count[d.w], 1)] = sv.w;
        }
    }
    grid_barrier();

    // ---- layer 1: x -> g_h0 ----
    {
        const float4* Wl4 = (const float4*)Wl;
        const float4* Wr4 = (const float4*)Wr;
        float4* sW4 = (float4*)sW;
#pragma unroll
        for (int i = tid; i < 2048; i += TPB)
            sW4[i] = (i < 1024) ? __ldg(&Wl4[i]) : __ldg(&Wr4[i - 1024]);
        __syncthreads();
        for (int tile = b; tile < NTILES; tile += NBLK)
            layer_tile<false>(x, sW, sWout, bl, bout, g_h0, tile, tid, sFeat);
    }
    grid_barrier();

    // ---- layer 2: g_h0 -> g_h1 ----
    {
        const float4* Wl4 = (const float4*)(Wl + HIDDEN * HIDDEN);
        const float4* Wr4 = (const float4*)(Wr + HIDDEN * HIDDEN);
        float4* sW4 = (float4*)sW;
#pragma unroll
        for (int i = tid; i < 2048; i += TPB)
            sW4[i] = (i < 1024) ? __ldg(&Wl4[i]) : __ldg(&Wr4[i - 1024]);
        __syncthreads();
        for (int tile = b; tile < NTILES; tile += NBLK)
            layer_tile<false>(g_h0, sW, sWout, bl + HIDDEN, bout, g_h1, tile, tid, sFeat);
    }
    grid_barrier();

    // ---- layer 3 + output projection: g_h1 -> out ----
    {
        const float4* Wl4 = (const float4*)(Wl + 2 * HIDDEN * HIDDEN);
        const float4* Wr4 = (const float4*)(Wr + 2 * HIDDEN * HIDDEN);
        float4* sW4 = (float4*)sW;
#pragma unroll
        for (int i = tid; i < 2048; i += TPB)
            sW4[i] = (i < 1024) ? __ldg(&Wl4[i]) : __ldg(&Wr4[i - 1024]);
        ((float4*)sWout)[tid] = __ldg(&((const float4*)Wout)[tid]);
        __syncthreads();
        for (int tile = b; tile < NTILES; tile += NBLK)
            layer_tile<true>(g_h1, sW, sWout, bl + 2 * HIDDEN, bout, out, tile, tid, sFeat);
    }
}

extern "C" void kernel_launch(void* const* d_in, const int* in_sizes, int n_in,
                              void* d_out, int out_size) {
    const float* x = (const float*)d_in[0];
    const int* ei = (const int*)d_in[1];
    const float* Wl = (const float*)d_in[2];
    const float* bl = (const float*)d_in[3];
    const float* Wr = (const float*)d_in[4];
    const float* Wout = (const float*)d_in[5];
    const float* bout = (const float*)d_in[6];
    float* out = (float*)d_out;

    const int SMEM_BYTES = (TILE_N * SROW + 128 * 64 + 64 * 16) * 4 + 64;  // ~70.7 KB
    static int configured = 0;
    if (!configured) {
        cudaFuncSetAttribute(fused_kernel,
                             cudaFuncAttributeMaxDynamicSharedMemorySize, SMEM_BYTES);
        configured = 1;
    }
    fused_kernel<<<NBLK, TPB, SMEM_BYTES>>>(x, ei, Wl, bl, Wr, Wout, bout, out);
}

// round 8
// speedup vs baseline: 16.6818x; 1.0781x over previous
#include <cuda_runtime.h>

#define N_NODES 50000
#define N_EDGES 800000
#define HIDDEN 64
#define OUT_DIM 16
#define NBLK 592          // 4 blocks/SM x 148 SMs
#define TPB 256
#define GSTRIDE (NBLK * TPB)
#define CHUNK 85          // ceil(50000/592)
#define TILE_N 64
#define NTILES 782        // ceil(50000/64)
#define SROW 132          // padded feature row: 128 data + 4 pad

// ---------------- device scratch ----------------
__device__ int g_count[N_NODES];
__device__ int g_off[N_NODES + 1];
__device__ int g_csr[N_EDGES];
__device__ int g_blocksum[NBLK];
__device__ int g_blockoff[NBLK];
__device__ unsigned g_bar_cnt;
__device__ unsigned g_bar_gen;
__device__ __align__(16) float g_h0[N_NODES * HIDDEN];
__device__ __align__(16) float g_h1[N_NODES * HIDDEN];

// ---------------- software grid barrier ----------------
__device__ __forceinline__ void grid_barrier() {
    __syncthreads();
    if (threadIdx.x == 0) {
        unsigned gen = *((volatile unsigned*)&g_bar_gen);
        __threadfence();
        unsigned a = atomicAdd(&g_bar_cnt, 1u);
        if (a == NBLK - 1) {
            g_bar_cnt = 0;
            __threadfence();
            atomicExch(&g_bar_gen, gen + 1u);
        } else {
            while (*((volatile unsigned*)&g_bar_gen) == gen) { __nanosleep(32); }
        }
        __threadfence();
    }
    __syncthreads();
}

__device__ __forceinline__ float4 fma4(float s, float4 w, float4 acc) {
    acc.x = fmaf(s, w.x, acc.x);
    acc.y = fmaf(s, w.y, acc.y);
    acc.z = fmaf(s, w.z, acc.z);
    acc.w = fmaf(s, w.w, acc.w);
    return acc;
}
__device__ __forceinline__ float4 relu4(float4 v) {
    v.x = fmaxf(v.x, 0.f); v.y = fmaxf(v.y, 0.f);
    v.z = fmaxf(v.z, 0.f); v.w = fmaxf(v.w, 0.f);
    return v;
}

// ---------------- pipelined gather-mean (16 threads/node) ----------------
__device__ __forceinline__ float4 gather_mean(const float4* __restrict__ x4,
                                              int node, int q) {
    int s = __ldg(&g_off[node]);
    int e = __ldg(&g_off[node + 1]);
    float4 acc = make_float4(0.f, 0.f, 0.f, 0.f);
    int i = s;
    int i0 = 0, i1 = 0, i2 = 0, i3 = 0;
    if (i + 4 <= e) {
        i0 = __ldg(&g_csr[i]);     i1 = __ldg(&g_csr[i + 1]);
        i2 = __ldg(&g_csr[i + 2]); i3 = __ldg(&g_csr[i + 3]);
    }
    while (i + 4 <= e) {
        float4 v0 = __ldg(&x4[i0 * 16 + q]);
        float4 v1 = __ldg(&x4[i1 * 16 + q]);
        float4 v2 = __ldg(&x4[i2 * 16 + q]);
        float4 v3 = __ldg(&x4[i3 * 16 + q]);
        i += 4;
        if (i + 4 <= e) {
            i0 = __ldg(&g_csr[i]);     i1 = __ldg(&g_csr[i + 1]);
            i2 = __ldg(&g_csr[i + 2]); i3 = __ldg(&g_csr[i + 3]);
        }
        acc.x += (v0.x + v1.x) + (v2.x + v3.x);
        acc.y += (v0.y + v1.y) + (v2.y + v3.y);
        acc.z += (v0.z + v1.z) + (v2.z + v3.z);
        acc.w += (v0.w + v1.w) + (v2.w + v3.w);
    }
    for (; i < e; i++) {
        int s0 = __ldg(&g_csr[i]);
        float4 v = __ldg(&x4[s0 * 16 + q]);
        acc.x += v.x; acc.y += v.y; acc.z += v.z; acc.w += v.w;
    }
    int deg = e - s;
    float invd = 1.0f / (float)(deg > 0 ? deg : 1);
    acc.x *= invd; acc.y *= invd; acc.z *= invd; acc.w *= invd;
    return acc;
}

// ---------------- one 64-node tile ----------------
// Weights read straight from global (L1-resident, broadcast pattern).
template <bool FINAL>
__device__ __forceinline__ void layer_tile(
    const float* __restrict__ xin,
    const float* __restrict__ Wlg,   // [64][64]
    const float* __restrict__ Wrg,   // [64][64]
    const float* __restrict__ Wog,   // [64][16] (FINAL)
    const float* __restrict__ bl,
    const float* __restrict__ bout,
    float* __restrict__ dst,
    int tile, int tid, float* sFeat) {
    int node0 = tile * TILE_N;
    // gather: sFeat[n][0:64]=agg, [64:128]=x
    {
        int ln = tid >> 4, q = tid & 15;
        const float4* x4 = (const float4*)xin;
#pragma unroll
        for (int sub = 0; sub < 4; sub++) {
            int n = sub * 16 + ln;
            int node = node0 + n;
            float4 agg = make_float4(0.f, 0.f, 0.f, 0.f);
            float4 xv = agg;
            if (node < N_NODES) {
                agg = gather_mean(x4, node, q);
                xv = __ldg(&x4[node * 16 + q]);
            }
            *(float4*)&sFeat[n * SROW + q * 4] = agg;
            *(float4*)&sFeat[n * SROW + 64 + q * 4] = xv;
        }
    }
    __syncthreads();

    // GEMM: 4 nodes x 4 features per thread
    int f0 = (tid & 15) * 4;
    int ngrp = tid >> 4;
    const float* r0 = &sFeat[(ngrp * 4 + 0) * SROW];
    const float* r1 = r0 + SROW;
    const float* r2 = r0 + 2 * SROW;
    const float* r3 = r0 + 3 * SROW;

    float4 bias;
    bias.x = __ldg(&bl[f0]); bias.y = __ldg(&bl[f0 + 1]);
    bias.z = __ldg(&bl[f0 + 2]); bias.w = __ldg(&bl[f0 + 3]);
    float4 acc0 = bias, acc1 = bias, acc2 = bias, acc3 = bias;

    // half 1: agg @ Wl  (K = 0..63, sFeat offset 0)
#pragma unroll 4
    for (int k4 = 0; k4 < 16; k4++) {
        float4 a0 = *(const float4*)&r0[k4 * 4];
        float4 a1 = *(const float4*)&r1[k4 * 4];
        float4 a2 = *(const float4*)&r2[k4 * 4];
        float4 a3 = *(const float4*)&r3[k4 * 4];
        const float* wb = &Wlg[k4 * 256 + f0];
        float4 w0 = __ldg((const float4*)&wb[0]);
        float4 w1 = __ldg((const float4*)&wb[64]);
        float4 w2 = __ldg((const float4*)&wb[128]);
        float4 w3 = __ldg((const float4*)&wb[192]);
        acc0 = fma4(a0.x, w0, acc0); acc0 = fma4(a0.y, w1, acc0);
        acc0 = fma4(a0.z, w2, acc0); acc0 = fma4(a0.w, w3, acc0);
        acc1 = fma4(a1.x, w0, acc1); acc1 = fma4(a1.y, w1, acc1);
        acc1 = fma4(a1.z, w2, acc1); acc1 = fma4(a1.w, w3, acc1);
        acc2 = fma4(a2.x, w0, acc2); acc2 = fma4(a2.y, w1, acc2);
        acc2 = fma4(a2.z, w2, acc2); acc2 = fma4(a2.w, w3, acc2);
        acc3 = fma4(a3.x, w0, acc3); acc3 = fma4(a3.y, w1, acc3);
        acc3 = fma4(a3.z, w2, acc3); acc3 = fma4(a3.w, w3, acc3);
    }
    // half 2: x @ Wr  (K = 0..63, sFeat offset 64)
#pragma unroll 4
    for (int k4 = 0; k4 < 16; k4++) {
        float4 a0 = *(const float4*)&r0[64 + k4 * 4];
        float4 a1 = *(const float4*)&r1[64 + k4 * 4];
        float4 a2 = *(const float4*)&r2[64 + k4 * 4];
        float4 a3 = *(const float4*)&r3[64 + k4 * 4];
        const float* wb = &Wrg[k4 * 256 + f0];
        float4 w0 = __ldg((const float4*)&wb[0]);
        float4 w1 = __ldg((const float4*)&wb[64]);
        float4 w2 = __ldg((const float4*)&wb[128]);
        float4 w3 = __ldg((const float4*)&wb[192]);
        acc0 = fma4(a0.x, w0, acc0); acc0 = fma4(a0.y, w1, acc0);
        acc0 = fma4(a0.z, w2, acc0); acc0 = fma4(a0.w, w3, acc0);
        acc1 = fma4(a1.x, w0, acc1); acc1 = fma4(a1.y, w1, acc1);
        acc1 = fma4(a1.z, w2, acc1); acc1 = fma4(a1.w, w3, acc1);
        acc2 = fma4(a2.x, w0, acc2); acc2 = fma4(a2.y, w1, acc2);
        acc2 = fma4(a2.z, w2, acc2); acc2 = fma4(a2.w, w3, acc2);
        acc3 = fma4(a3.x, w0, acc3); acc3 = fma4(a3.y, w1, acc3);
        acc3 = fma4(a3.z, w2, acc3); acc3 = fma4(a3.w, w3, acc3);
    }
    acc0 = relu4(acc0); acc1 = relu4(acc1); acc2 = relu4(acc2); acc3 = relu4(acc3);

    int nb = ngrp * 4;
    if (!FINAL) {
        int gn = node0 + nb;
        if (gn + 0 < N_NODES) *(float4*)&dst[(gn + 0) * 64 + f0] = acc0;
        if (gn + 1 < N_NODES) *(float4*)&dst[(gn + 1) * 64 + f0] = acc1;
        if (gn + 2 < N_NODES) *(float4*)&dst[(gn + 2) * 64 + f0] = acc2;
        if (gn + 3 < N_NODES) *(float4*)&dst[(gn + 3) * 64 + f0] = acc3;
        __syncthreads();
    } else {
        __syncthreads();
        *(float4*)&sFeat[(nb + 0) * SROW + f0] = acc0;
        *(float4*)&sFeat[(nb + 1) * SROW + f0] = acc1;
        *(float4*)&sFeat[(nb + 2) * SROW + f0] = acc2;
        *(float4*)&sFeat[(nb + 3) * SROW + f0] = acc3;
        __syncthreads();
        int n = tid >> 2;
        int o0 = (tid & 3) * 4;
        float4 oacc;
        oacc.x = __ldg(&bout[o0]); oacc.y = __ldg(&bout[o0 + 1]);
        oacc.z = __ldg(&bout[o0 + 2]); oacc.w = __ldg(&bout[o0 + 3]);
        const float* yr = &sFeat[n * SROW];
#pragma unroll 4
        for (int k4 = 0; k4 < 16; k4++) {
            float4 yv = *(const float4*)&yr[k4 * 4];
            const float* wb = &Wog[k4 * 64 + o0];
            float4 w0 = __ldg((const float4*)&wb[0]);
            float4 w1 = __ldg((const float4*)&wb[16]);
            float4 w2 = __ldg((const float4*)&wb[32]);
            float4 w3 = __ldg((const float4*)&wb[48]);
            oacc = fma4(yv.x, w0, oacc); oacc = fma4(yv.y, w1, oacc);
            oacc = fma4(yv.z, w2, oacc); oacc = fma4(yv.w, w3, oacc);
        }
        int gn = node0 + n;
        if (gn < N_NODES) *(float4*)&dst[gn * OUT_DIM + o0] = oacc;
        __syncthreads();
    }
}

// ---------------- persistent kernel ----------------
__global__ void __launch_bounds__(TPB, 4) fused_kernel(
    const float* __restrict__ x, const int* __restrict__ ei,
    const float* __restrict__ Wl, const float* __restrict__ bl,
    const float* __restrict__ Wr, const float* __restrict__ Wout,
    const float* __restrict__ bout, float* __restrict__ out) {
    __shared__ float sFeat[TILE_N * SROW];   // 33.8 KB
    __shared__ int sInts[8];

    int tid = threadIdx.x;
    int b = blockIdx.x;
    int gtid = b * TPB + tid;
    int lane = tid & 31, w = tid >> 5;

    // phase 0: zero counts
    for (int i = gtid; i < N_NODES; i += GSTRIDE) g_count[i] = 0;
    grid_barrier();

    // phase 1: histogram
    {
        const int4* dst4 = (const int4*)(ei + N_EDGES);
        for (int t = gtid; t < N_EDGES / 4; t += GSTRIDE) {
            int4 d = __ldg(&dst4[t]);
            atomicAdd(&g_count[d.x], 1);
            atomicAdd(&g_count[d.y], 1);
            atomicAdd(&g_count[d.z], 1);
            atomicAdd(&g_count[d.w], 1);
        }
    }
    grid_barrier();

    // phase 2a: block-local exclusive scan of CHUNK counts
    {
        int base = b * CHUNK;
        int idx = base + tid;
        int v = (tid < CHUNK && idx < N_NODES) ? g_count[idx] : 0;
        int s = v;
#pragma unroll
        for (int d = 1; d < 32; d <<= 1) {
            int tv = __shfl_up_sync(0xffffffffu, s, d);
            if (lane >= d) s += tv;
        }
        if (lane == 31) sInts[w] = s;
        __syncthreads();
        if (tid == 0) {
            int acc = 0;
#pragma unroll
            for (int k = 0; k < 8; k++) { int t2 = sInts[k]; sInts[k] = acc; acc += t2; }
        }
        __syncthreads();
        int incl = s + sInts[w];
        if (tid < CHUNK && idx < N_NODES) g_off[idx] = incl - v;
        if (tid == TPB - 1) g_blocksum[b] = incl;
    }
    grid_barrier();

    // phase 2b: block 0 scans the NBLK block sums (3 per thread)
    if (b == 0) {
        int base2 = tid * 3;
        int v0 = (base2 + 0 < NBLK) ? g_blocksum[base2 + 0] : 0;
        int v1 = (base2 + 1 < NBLK) ? g_blocksum[base2 + 1] : 0;
        int v2 = (base2 + 2 < NBLK) ? g_blocksum[base2 + 2] : 0;
        int tsum = v0 + v1 + v2;
        int s = tsum;
#pragma unroll
        for (int d = 1; d < 32; d <<= 1) {
            int tv = __shfl_up_sync(0xffffffffu, s, d);
            if (lane >= d) s += tv;
        }
        if (lane == 31) sInts[w] = s;
        __syncthreads();
        if (tid == 0) {
            int acc = 0;
#pragma unroll
            for (int k = 0; k < 8; k++) { int t2 = sInts[k]; sInts[k] = acc; acc += t2; }
        }
        __syncthreads();
        int excl = (s - tsum) + sInts[w];
        if (base2 + 0 < NBLK) { g_blockoff[base2 + 0] = excl; excl += v0; }
        if (base2 + 1 < NBLK) { g_blockoff[base2 + 1] = excl; excl += v1; }
        if (base2 + 2 < NBLK) { g_blockoff[base2 + 2] = excl; excl += v2; }
    }
    grid_barrier();

    // phase 2c: add block offsets; init fill cursors
    {
        int off = g_blockoff[b];
        int idx = b * CHUNK + tid;
        if (tid < CHUNK && idx < N_NODES) {
            int o = g_off[idx] + off;
            g_off[idx] = o;
            g_count[idx] = o;
        }
        if (gtid == 0) g_off[N_NODES] = N_EDGES;
    }
    grid_barrier();

    // phase 3: fill CSR
    {
        const int4* src4 = (const int4*)ei;
        const int4* dst4 = (const int4*)(ei + N_EDGES);
        for (int t = gtid; t < N_EDGES / 4; t += GSTRIDE) {
            int4 sv = __ldg(&src4[t]);
            int4 d = __ldg(&dst4[t]);
            g_csr[atomicAdd(&g_count[d.x], 1)] = sv.x;
            g_csr[atomicAdd(&g_count[d.y], 1)] = sv.y;
            g_csr[atomicAdd(&g_count[d.z], 1)] = sv.z;
            g_csr[atomicAdd(&g_count[d.w], 1)] = sv.w;
        }
    }
    grid_barrier();

    // ---- layer 1: x -> g_h0 ----
    for (int tile = b; tile < NTILES; tile += NBLK)
        layer_tile<false>(x, Wl, Wr, Wout, bl, bout, g_h0, tile, tid, sFeat);
    grid_barrier();

    // ---- layer 2: g_h0 -> g_h1 ----
    for (int tile = b; tile < NTILES; tile += NBLK)
        layer_tile<false>(g_h0, Wl + 4096, Wr + 4096, Wout,
                          bl + HIDDEN, bout, g_h1, tile, tid, sFeat);
    grid_barrier();

    // ---- layer 3 + output projection: g_h1 -> out ----
    for (int tile = b; tile < NTILES; tile += NBLK)
        layer_tile<true>(g_h1, Wl + 8192, Wr + 8192, Wout,
                         bl + 2 * HIDDEN, bout, out, tile, tid, sFeat);
}

extern "C" void kernel_launch(void* const* d_in, const int* in_sizes, int n_in,
                              void* d_out, int out_size) {
    const float* x = (const float*)d_in[0];
    const int* ei = (const int*)d_in[1];
    const float* Wl = (const float*)d_in[2];
    const float* bl = (const float*)d_in[3];
    const float* Wr = (const float*)d_in[4];
    const float* Wout = (const float*)d_in[5];
    const float* bout = (const float*)d_in[6];
    float* out = (float*)d_out;

    fused_kernel<<<NBLK, TPB>>>(x, ei, Wl, bl, Wr, Wout, bout, out);
}